// round 13
// baseline (speedup 1.0000x reference)
#include <cuda_runtime.h>
#include <math.h>

#define TP 98
#define PT 100
typedef unsigned long long ull;
typedef unsigned uint32;

__device__ __align__(16) float g_xn[96*96*96];
__device__ __align__(16) float g_M[8*96*96];   // transposed + tf32-rounded: [h][j][c]
__device__ __align__(16) float g_N[8*96*96];   // transposed + tf32-rounded: [h][l][c]
__device__ __align__(16) float g_u[8*96];
__device__ __align__(16) float g_w[8*96];
__device__ __align__(16) float g_cc[8];
__device__ __align__(16) float g_bp[96];
__device__ __align__(16) float g_part[8*96*96*96];

__device__ __forceinline__ ull pack2(float a) {
    ull r; asm("mov.b64 %0, {%1, %2};" : "=l"(r) : "f"(a), "f"(a)); return r;
}
__device__ __forceinline__ ull fma2(ull a, ull b, ull c) {
    ull d; asm("fma.rn.f32x2 %0, %1, %2, %3;" : "=l"(d) : "l"(a), "l"(b), "l"(c)); return d;
}
__device__ __forceinline__ float2 unpk(ull p) {
    float2 f; asm("mov.b64 {%0, %1}, %2;" : "=f"(f.x), "=f"(f.y) : "l"(p)); return f;
}
__device__ __forceinline__ uint32 f2tf(float f) {
    uint32 r; asm("cvt.rna.tf32.f32 %0, %1;" : "=r"(r) : "f"(f)); return r;
}
__device__ __forceinline__ void mma8(float c[4], uint32 a0, uint32 a1, uint32 a2, uint32 a3,
                                     uint32 b0, uint32 b1) {
    asm("mma.sync.aligned.m16n8k8.row.col.f32.tf32.tf32.f32 "
        "{%0,%1,%2,%3},{%4,%5,%6,%7},{%8,%9},{%0,%1,%2,%3};"
        : "+f"(c[0]), "+f"(c[1]), "+f"(c[2]), "+f"(c[3])
        : "r"(a0), "r"(a1), "r"(a2), "r"(a3), "r"(b0), "r"(b1));
}

// Warp GEMM: C(16x48) = A(rows r0..r0+15, k=0..95) x B([n][k] layout), both pitch PT.
__device__ __forceinline__ void wgemm(const uint32* __restrict__ A,
                                      const uint32* __restrict__ B,
                                      int r0, int c0, int lane, float c[6][4]) {
    const int g = lane >> 2, tg = lane & 3;
    const uint32* Ap = A + (r0 + g) * PT + tg;
    const uint32* Bp = B + (c0 + g) * PT + tg;
#pragma unroll
    for (int k8 = 0; k8 < 12; ++k8) {
        const int kb = k8 * 8;
        uint32 a0 = Ap[kb], a1 = Ap[8 * PT + kb], a2 = Ap[kb + 4], a3 = Ap[8 * PT + kb + 4];
#pragma unroll
        for (int n = 0; n < 6; ++n) {
            uint32 b0 = Bp[n * 8 * PT + kb], b1 = Bp[n * 8 * PT + kb + 4];
            mma8(c[n], a0, a1, a2, a3, b0, b1);
        }
    }
}

// FFMA2 GEMM for pre
template<int AMODE, int PB>
__device__ __forceinline__ void gemm96(const float* __restrict__ A,
                                       const float* __restrict__ B,
                                       int i0, int j0, ull acc[6][3]) {
    const float* Bj = B + j0;
#pragma unroll 2
    for (int k = 0; k < 96; k += 2) {
        ull b0[3], b1[3];
#pragma unroll
        for (int p = 0; p < 3; ++p) {
            b0[p] = *(const ull*)(Bj + k * PB + 2 * p);
            b1[p] = *(const ull*)(Bj + (k + 1) * PB + 2 * p);
        }
        ull a0[6], a1[6];
        if (AMODE == 0) {
#pragma unroll
            for (int ii = 0; ii < 3; ++ii) {
                float2 f0 = *(const float2*)(A + k * TP + i0 + 2 * ii);
                float2 f1 = *(const float2*)(A + (k + 1) * TP + i0 + 2 * ii);
                a0[2*ii] = pack2(f0.x); a0[2*ii+1] = pack2(f0.y);
                a1[2*ii] = pack2(f1.x); a1[2*ii+1] = pack2(f1.y);
            }
        } else {
#pragma unroll
            for (int i = 0; i < 6; ++i) {
                float2 f = *(const float2*)(A + (i0 + i) * 96 + k);
                a0[i] = pack2(f.x); a1[i] = pack2(f.y);
            }
        }
#pragma unroll
        for (int i = 0; i < 6; ++i)
#pragma unroll
            for (int p = 0; p < 3; ++p)
                acc[i][p] = fma2(a0[i], b0[p], acc[i][p]);
#pragma unroll
        for (int i = 0; i < 6; ++i)
#pragma unroll
            for (int p = 0; p < 3; ++p)
                acc[i][p] = fma2(a1[i], b1[p], acc[i][p]);
    }
}

// ---- 1) GroupNorm
__global__ void gn_kernel(const float* __restrict__ x,
                          const float* __restrict__ gamma,
                          const float* __restrict__ beta) {
    const int b = blockIdx.x, g = blockIdx.y, tid = threadIdx.x;
    const float* xp = x + b * 9216 + g * 1152;
    float vals[9], sum = 0.f, sq = 0.f;
#pragma unroll
    for (int t = 0; t < 9; ++t) {
        float v = xp[tid + t * 128];
        vals[t] = v; sum += v; sq += v * v;
    }
    __shared__ float s1[128], s2[128];
    s1[tid] = sum; s2[tid] = sq;
    __syncthreads();
    for (int o = 64; o > 0; o >>= 1) {
        if (tid < o) { s1[tid] += s1[tid + o]; s2[tid] += s2[tid + o]; }
        __syncthreads();
    }
    const float mean = s1[0] * (1.f / 1152.f);
    const float var  = s2[0] * (1.f / 1152.f) - mean * mean;
    const float rstd = rsqrtf(var + 1e-5f);
#pragma unroll
    for (int t = 0; t < 9; ++t) {
        int e = tid + t * 128;
        int ch = g * 12 + e / 96;
        g_xn[b * 9216 + g * 1152 + e] = (vals[t] - mean) * rstd * gamma[ch] + beta[ch];
    }
}

// ---- 2) Precompute (stores M^T, N^T tf32-rounded)
__global__ __launch_bounds__(256, 1)
void pre_kernel(const float* __restrict__ Wq, const float* __restrict__ bq,
                const float* __restrict__ Wk, const float* __restrict__ bk,
                const float* __restrict__ Wv, const float* __restrict__ bv,
                const float* __restrict__ Wo, const float* __restrict__ bo) {
    const int h = blockIdx.x, m = blockIdx.y, tid = threadIdx.x;
    extern __shared__ float sm[];
    float* bufA = sm;
    float* bufB = sm + 9216;
    const float inv = rsqrtf(96.0f);
    const int tx = tid & 15, ty = tid >> 4;
    const int i0 = ty * 6, j0 = tx * 6;

    if (m == 0) {
        for (int idx = tid; idx < 9216; idx += 256) {
            int i = idx / 96, d = idx % 96;
            bufA[idx]        = Wq[i * 768 + h * 96 + d];
            bufB[d * TP + i] = Wk[i * 768 + h * 96 + d];
        }
        __syncthreads();
        ull acc[6][3];
#pragma unroll
        for (int i = 0; i < 6; ++i) for (int p = 0; p < 3; ++p) acc[i][p] = 0ULL;
        gemm96<1, TP>(bufA, bufB, i0, j0, acc);   // M = Wq_h Wk_h^T
#pragma unroll
        for (int i = 0; i < 6; ++i)
#pragma unroll
            for (int p = 0; p < 3; ++p) {
                float2 f = unpk(acc[i][p]);
                g_M[h * 9216 + (j0 + 2 * p)     * 96 + (i0 + i)] = __uint_as_float(f2tf(f.x * inv));
                g_M[h * 9216 + (j0 + 2 * p + 1) * 96 + (i0 + i)] = __uint_as_float(f2tf(f.y * inv));
            }
        if (tid < 96) {
            float a = 0.f, c = 0.f;
            for (int d = 0; d < 96; ++d) {
                a += bufA[tid * 96 + d] * bk[h * 96 + d];
                c += bufB[d * TP + tid] * bq[h * 96 + d];
            }
            g_u[h * 96 + tid] = a * inv;
            g_w[h * 96 + tid] = c * inv;
        }
        if (tid == 0) {
            float cs = 0.f;
            for (int d = 0; d < 96; ++d) cs += bq[h * 96 + d] * bk[h * 96 + d];
            g_cc[h] = cs * inv;
        }
        if (h == 0 && tid >= 128 && tid < 224) {
            int c = tid - 128;
            float s = bo[c];
            for (int j = 0; j < 768; ++j) s += bv[j] * Wo[j * 96 + c];
            g_bp[c] = s;
        }
    } else {
        for (int idx = tid; idx < 9216; idx += 256) {
            int i = idx / 96, d = idx % 96;
            bufA[idx] = Wv[i * 768 + h * 96 + d];
            bufB[idx] = Wo[h * 9216 + idx];
        }
        __syncthreads();
        ull acc[6][3];
#pragma unroll
        for (int i = 0; i < 6; ++i) for (int p = 0; p < 3; ++p) acc[i][p] = 0ULL;
        gemm96<1, 96>(bufA, bufB, i0, j0, acc);   // N = Wv_h Wo_h
#pragma unroll
        for (int i = 0; i < 6; ++i)
#pragma unroll
            for (int p = 0; p < 3; ++p) {
                float2 f = unpk(acc[i][p]);
                g_N[h * 9216 + (j0 + 2 * p)     * 96 + (i0 + i)] = __uint_as_float(f2tf(f.x));
                g_N[h * 9216 + (j0 + 2 * p + 1) * 96 + (i0 + i)] = __uint_as_float(f2tf(f.y));
            }
    }
}

// ---- 3) Attention via tf32 mma.sync, occ=2 (R10 verbatim)
__global__ __launch_bounds__(384, 2)
void attn_kernel() {
    const int b = blockIdx.x, h = blockIdx.y;
    extern __shared__ uint32 smu[];
    uint32* tS = smu;              // t (tf32), later X2^T ; pads: rv,zv,uv,wv
    uint32* W  = smu + 96 * PT;    // M^T, later P        ; pads: pmx,psm
    uint32* Y  = smu + 2 * 96 * PT;// X1, later N^T
    float* tSf = (float*)tS;
    float* Wf  = (float*)W;
#define RV(i)      tSf[(i) * PT + 96]
#define ZV(i)      tSf[(i) * PT + 97]
#define UV(i)      tSf[(i) * PT + 98]
#define WV(i)      tSf[(i) * PT + 99]
#define PMX(hf, i) Wf[(i) * PT + 96 + (hf)]
#define PSM(hf, i) Wf[(i) * PT + 98 + (hf)]

    const int tid = threadIdx.x;
    const int lane = tid & 31, wid = tid >> 5;
    const int r0 = (wid >> 1) * 16, c0 = (wid & 1) * 48;
    const int g = lane >> 2, tg = lane & 3;
    const float NEGINF = __int_as_float(0xff800000);

    {
        const float4* xb4 = (const float4*)(g_xn + b * 9216);
        const float4* Mh4 = (const float4*)(g_M + h * 9216);
#pragma unroll
        for (int r = 0; r < 6; ++r) {
            int idx = tid + r * 384;
            int rr = idx / 24, q4 = idx - rr * 24;
            float4 xv = xb4[idx];
            uint4 tv = make_uint4(f2tf(xv.x), f2tf(xv.y), f2tf(xv.z), f2tf(xv.w));
            *(uint4*)(tS + rr * PT + q4 * 4) = tv;
            *(float4*)(Wf + rr * PT + q4 * 4) = Mh4[idx];
        }
        if (tid < 96) { UV(tid) = g_u[h * 96 + tid]; WV(tid) = g_w[h * 96 + tid]; }
    }
    __syncthreads();

    if (tid < 96) {
        float a = 0.f;
        for (int c = 0; c < 96; ++c) a += __uint_as_float(tS[tid * PT + c]) * UV(c);
        RV(tid) = a;
    } else if (tid < 192) {
        const int j = tid - 96;
        float a = 0.f;
        for (int c = 0; c < 96; ++c) a += __uint_as_float(tS[j * PT + c]) * WV(c);
        ZV(j) = a;
    }

    {
        float c[6][4];
#pragma unroll
        for (int n = 0; n < 6; ++n) for (int q = 0; q < 4; ++q) c[n][q] = 0.f;
        wgemm(tS, W, r0, c0, lane, c);
#pragma unroll
        for (int n = 0; n < 6; ++n) {
            const int col = c0 + n * 8 + 2 * tg, row = r0 + g;
            Y[row * PT + col]           = f2tf(c[n][0]);
            Y[row * PT + col + 1]       = f2tf(c[n][1]);
            Y[(row + 8) * PT + col]     = f2tf(c[n][2]);
            Y[(row + 8) * PT + col + 1] = f2tf(c[n][3]);
        }
    }
    __syncthreads();   // S0: X1 ready; M^T dead

    float sv[6][4];
    {
#pragma unroll
        for (int n = 0; n < 6; ++n) for (int q = 0; q < 4; ++q) sv[n][q] = 0.f;
        wgemm(Y, tS, r0, c0, lane, sv);
    }
    const int i0r = r0 + g, i1r = r0 + g + 8;
    const float ccv = g_cc[h];
    {
        const float ri0 = RV(i0r) + ccv, ri1 = RV(i1r) + ccv;
        float m0 = NEGINF, m1 = NEGINF;
#pragma unroll
        for (int n = 0; n < 6; ++n) {
            const int j0 = c0 + n * 8 + 2 * tg, j1 = j0 + 1;
            float v00 = (j0 <= i0r) ? sv[n][0] + ri0 + ZV(j0) : NEGINF;
            float v01 = (j1 <= i0r) ? sv[n][1] + ri0 + ZV(j1) : NEGINF;
            float v10 = (j0 <= i1r) ? sv[n][2] + ri1 + ZV(j0) : NEGINF;
            float v11 = (j1 <= i1r) ? sv[n][3] + ri1 + ZV(j1) : NEGINF;
            sv[n][0] = v00; sv[n][1] = v01; sv[n][2] = v10; sv[n][3] = v11;
            m0 = fmaxf(m0, fmaxf(v00, v01));
            m1 = fmaxf(m1, fmaxf(v10, v11));
        }
        m0 = fmaxf(m0, __shfl_xor_sync(0xffffffffu, m0, 1));
        m0 = fmaxf(m0, __shfl_xor_sync(0xffffffffu, m0, 2));
        m1 = fmaxf(m1, __shfl_xor_sync(0xffffffffu, m1, 1));
        m1 = fmaxf(m1, __shfl_xor_sync(0xffffffffu, m1, 2));
        if (tg == 0) { PMX(wid & 1, i0r) = m0; PMX(wid & 1, i1r) = m1; }
    }
    __syncthreads();   // S1

    {
        const float m0f = fmaxf(PMX(0, i0r), PMX(1, i0r));
        const float m1f = fmaxf(PMX(0, i1r), PMX(1, i1r));
        float s0 = 0.f, s1 = 0.f;
#pragma unroll
        for (int n = 0; n < 6; ++n) {
            float e0 = __expf(sv[n][0] - m0f), e1 = __expf(sv[n][1] - m0f);
            float e2 = __expf(sv[n][2] - m1f), e3 = __expf(sv[n][3] - m1f);
            sv[n][0] = e0; sv[n][1] = e1; sv[n][2] = e2; sv[n][3] = e3;
            s0 += e0 + e1; s1 += e2 + e3;
        }
        s0 += __shfl_xor_sync(0xffffffffu, s0, 1);
        s0 += __shfl_xor_sync(0xffffffffu, s0, 2);
        s1 += __shfl_xor_sync(0xffffffffu, s1, 1);
        s1 += __shfl_xor_sync(0xffffffffu, s1, 2);
        if (tg == 0) { PSM(wid & 1, i0r) = s0; PSM(wid & 1, i1r) = s1; }
    }
    // stage N^T into Y (pre-rounded copy)
    {
        const float4* Nh4 = (const float4*)(g_N + h * 9216);
        float* Yf = (float*)Y;
#pragma unroll
        for (int r = 0; r < 6; ++r) {
            int idx = tid + r * 384;
            int rr = idx / 24, q4 = idx - rr * 24;
            *(float4*)(Yf + rr * PT + q4 * 4) = Nh4[idx];
        }
    }
    __syncthreads();   // S2: sums + N^T ready

    {
        const float is0 = 1.0f / (PSM(0, i0r) + PSM(1, i0r));
        const float is1 = 1.0f / (PSM(0, i1r) + PSM(1, i1r));
#pragma unroll
        for (int n = 0; n < 6; ++n) {
            const int col = c0 + n * 8 + 2 * tg;
            W[i0r * PT + col]     = f2tf(sv[n][0] * is0);
            W[i0r * PT + col + 1] = f2tf(sv[n][1] * is0);
            W[i1r * PT + col]     = f2tf(sv[n][2] * is1);
            W[i1r * PT + col + 1] = f2tf(sv[n][3] * is1);
        }
    }

    {
        float c[6][4];
#pragma unroll
        for (int n = 0; n < 6; ++n) for (int q = 0; q < 4; ++q) c[n][q] = 0.f;
        wgemm(tS, Y, r0, c0, lane, c);
        __syncthreads();   // S3
#pragma unroll
        for (int n = 0; n < 6; ++n) {
            const int col = c0 + n * 8 + 2 * tg, row = r0 + g;
            tS[col * PT + row]           = f2tf(c[n][0]);
            tS[(col + 1) * PT + row]     = f2tf(c[n][1]);
            tS[col * PT + row + 8]       = f2tf(c[n][2]);
            tS[(col + 1) * PT + row + 8] = f2tf(c[n][3]);
        }
    }
    __syncthreads();   // S4: X2^T ready

    {
        float c[6][4];
#pragma unroll
        for (int n = 0; n < 6; ++n) for (int q = 0; q < 4; ++q) c[n][q] = 0.f;
        wgemm(W, tS, r0, c0, lane, c);
        float* dst = g_part + (h * 96 + b) * 9216;
#pragma unroll
        for (int n = 0; n < 6; ++n) {
            const int l0 = c0 + n * 8 + 2 * tg, row = r0 + g;
            *(float2*)(dst + row * 96 + l0)       = make_float2(c[n][0], c[n][1]);
            *(float2*)(dst + (row + 8) * 96 + l0) = make_float2(c[n][2], c[n][3]);
        }
    }
#undef RV
#undef ZV
#undef UV
#undef WV
#undef PMX
#undef PSM
}

// ---- 4) Fused head-reduce + broadcast: out[b,j,s,l] = sum_h part[h,j,s,l] + bp[l] + xn[b,j,l]
// grid (6 bt, 96 j), 384 thr. Blocks sharing j have consecutive bids -> L2 reuse of part reads.
__global__ __launch_bounds__(384)
void redbc_kernel(float* __restrict__ out) {
    __shared__ __align__(16) float O_s[9216];
    const int bt = blockIdx.x, j = blockIdx.y;
    const int tid = threadIdx.x;
    float4* Os4 = (float4*)O_s;
    const float4* bp4 = (const float4*)g_bp;
#pragma unroll
    for (int r = 0; r < 6; ++r) {
        int idx = tid + r * 384;                 // 2304 float4s
        float4 a = bp4[idx % 24];
#pragma unroll
        for (int h = 0; h < 8; ++h) {
            float4 p = ((const float4*)(g_part + (size_t)h * 884736 + (size_t)j * 9216))[idx];
            a.x += p.x; a.y += p.y; a.z += p.z; a.w += p.w;
        }
        Os4[idx] = a;
    }
    const int b_i = tid / 24;       // 0..15
    const int q   = tid - b_i * 24; // 0..23
    const int bg  = bt * 16 + b_i;
    const float4 xnv = *(const float4*)(g_xn + (size_t)bg * 9216 + j * 96 + q * 4);
    __syncthreads();
    float* dst = out + ((size_t)bg * 96 + (size_t)j) * 9216 + q * 4;
#pragma unroll 8
    for (int s = 0; s < 96; ++s) {
        float4 o = Os4[s * 24 + q];
        float4 v = make_float4(o.x + xnv.x, o.y + xnv.y, o.z + xnv.z, o.w + xnv.w);
        __stcs((float4*)(dst + s * 96), v);
    }
}

extern "C" void kernel_launch(void* const* d_in, const int* in_sizes, int n_in,
                              void* d_out, int out_size) {
    const float* x     = (const float*)d_in[0];
    const float* Wq    = (const float*)d_in[1];
    const float* bq    = (const float*)d_in[2];
    const float* Wk    = (const float*)d_in[3];
    const float* bk    = (const float*)d_in[4];
    const float* Wv    = (const float*)d_in[5];
    const float* bv    = (const float*)d_in[6];
    const float* Wo    = (const float*)d_in[7];
    const float* bo    = (const float*)d_in[8];
    const float* gamma = (const float*)d_in[9];
    const float* beta  = (const float*)d_in[10];
    float* out = (float*)d_out;

    const int pre_smem  = (9216 + 96 * TP) * 4;
    const int attn_smem = 3 * 96 * PT * 4;   // 115,200 B -> 2 CTAs/SM
    cudaFuncSetAttribute(pre_kernel,  cudaFuncAttributeMaxDynamicSharedMemorySize, pre_smem);
    cudaFuncSetAttribute(attn_kernel, cudaFuncAttributeMaxDynamicSharedMemorySize, attn_smem);

    gn_kernel<<<dim3(96, 8), 128>>>(x, gamma, beta);
    pre_kernel<<<dim3(8, 2), 256, pre_smem>>>(Wq, bq, Wk, bk, Wv, bv, Wo, bo);
    attn_kernel<<<dim3(96, 8), 384, attn_smem>>>();
    redbc_kernel<<<dim3(6, 96), 384>>>(out);
}

// round 14
// speedup vs baseline: 1.0277x; 1.0277x over previous
#include <cuda_runtime.h>
#include <math.h>

#define TP 98
#define PT 100
typedef unsigned long long ull;
typedef unsigned uint32;

__device__ __align__(16) float g_xn[96*96*96];
__device__ __align__(16) float g_M[8*96*96];   // transposed + tf32-rounded: [h][j][c]
__device__ __align__(16) float g_N[8*96*96];   // transposed + tf32-rounded: [h][l][c]
__device__ __align__(16) float g_u[8*96];
__device__ __align__(16) float g_w[8*96];
__device__ __align__(16) float g_cc[8];
__device__ __align__(16) float g_bp[96];
__device__ __align__(16) float g_part[8*96*96*96];
__device__ __align__(16) float g_O[96*96*96];

__device__ __forceinline__ ull pack2(float a) {
    ull r; asm("mov.b64 %0, {%1, %2};" : "=l"(r) : "f"(a), "f"(a)); return r;
}
__device__ __forceinline__ ull fma2(ull a, ull b, ull c) {
    ull d; asm("fma.rn.f32x2 %0, %1, %2, %3;" : "=l"(d) : "l"(a), "l"(b), "l"(c)); return d;
}
__device__ __forceinline__ float2 unpk(ull p) {
    float2 f; asm("mov.b64 {%0, %1}, %2;" : "=f"(f.x), "=f"(f.y) : "l"(p)); return f;
}
__device__ __forceinline__ uint32 f2tf(float f) {
    uint32 r; asm("cvt.rna.tf32.f32 %0, %1;" : "=r"(r) : "f"(f)); return r;
}
__device__ __forceinline__ void mma8(float c[4], uint32 a0, uint32 a1, uint32 a2, uint32 a3,
                                     uint32 b0, uint32 b1) {
    asm("mma.sync.aligned.m16n8k8.row.col.f32.tf32.tf32.f32 "
        "{%0,%1,%2,%3},{%4,%5,%6,%7},{%8,%9},{%0,%1,%2,%3};"
        : "+f"(c[0]), "+f"(c[1]), "+f"(c[2]), "+f"(c[3])
        : "r"(a0), "r"(a1), "r"(a2), "r"(a3), "r"(b0), "r"(b1));
}

// Warp GEMM: C(16x48) = A(rows r0..r0+15, k=0..95) x B([n][k] layout), both pitch PT.
__device__ __forceinline__ void wgemm(const uint32* __restrict__ A,
                                      const uint32* __restrict__ B,
                                      int r0, int c0, int lane, float c[6][4]) {
    const int g = lane >> 2, tg = lane & 3;
    const uint32* Ap = A + (r0 + g) * PT + tg;
    const uint32* Bp = B + (c0 + g) * PT + tg;
#pragma unroll
    for (int k8 = 0; k8 < 12; ++k8) {
        const int kb = k8 * 8;
        uint32 a0 = Ap[kb], a1 = Ap[8 * PT + kb], a2 = Ap[kb + 4], a3 = Ap[8 * PT + kb + 4];
#pragma unroll
        for (int n = 0; n < 6; ++n) {
            uint32 b0 = Bp[n * 8 * PT + kb], b1 = Bp[n * 8 * PT + kb + 4];
            mma8(c[n], a0, a1, a2, a3, b0, b1);
        }
    }
}

// FFMA2 GEMM for pre
template<int AMODE, int PB>
__device__ __forceinline__ void gemm96(const float* __restrict__ A,
                                       const float* __restrict__ B,
                                       int i0, int j0, ull acc[6][3]) {
    const float* Bj = B + j0;
#pragma unroll 2
    for (int k = 0; k < 96; k += 2) {
        ull b0[3], b1[3];
#pragma unroll
        for (int p = 0; p < 3; ++p) {
            b0[p] = *(const ull*)(Bj + k * PB + 2 * p);
            b1[p] = *(const ull*)(Bj + (k + 1) * PB + 2 * p);
        }
        ull a0[6], a1[6];
        if (AMODE == 0) {
#pragma unroll
            for (int ii = 0; ii < 3; ++ii) {
                float2 f0 = *(const float2*)(A + k * TP + i0 + 2 * ii);
                float2 f1 = *(const float2*)(A + (k + 1) * TP + i0 + 2 * ii);
                a0[2*ii] = pack2(f0.x); a0[2*ii+1] = pack2(f0.y);
                a1[2*ii] = pack2(f1.x); a1[2*ii+1] = pack2(f1.y);
            }
        } else {
#pragma unroll
            for (int i = 0; i < 6; ++i) {
                float2 f = *(const float2*)(A + (i0 + i) * 96 + k);
                a0[i] = pack2(f.x); a1[i] = pack2(f.y);
            }
        }
#pragma unroll
        for (int i = 0; i < 6; ++i)
#pragma unroll
            for (int p = 0; p < 3; ++p)
                acc[i][p] = fma2(a0[i], b0[p], acc[i][p]);
#pragma unroll
        for (int i = 0; i < 6; ++i)
#pragma unroll
            for (int p = 0; p < 3; ++p)
                acc[i][p] = fma2(a1[i], b1[p], acc[i][p]);
    }
}

// ---- 1) GroupNorm
__global__ void gn_kernel(const float* __restrict__ x,
                          const float* __restrict__ gamma,
                          const float* __restrict__ beta) {
    const int b = blockIdx.x, g = blockIdx.y, tid = threadIdx.x;
    const float* xp = x + b * 9216 + g * 1152;
    float vals[9], sum = 0.f, sq = 0.f;
#pragma unroll
    for (int t = 0; t < 9; ++t) {
        float v = xp[tid + t * 128];
        vals[t] = v; sum += v; sq += v * v;
    }
    __shared__ float s1[128], s2[128];
    s1[tid] = sum; s2[tid] = sq;
    __syncthreads();
    for (int o = 64; o > 0; o >>= 1) {
        if (tid < o) { s1[tid] += s1[tid + o]; s2[tid] += s2[tid + o]; }
        __syncthreads();
    }
    const float mean = s1[0] * (1.f / 1152.f);
    const float var  = s2[0] * (1.f / 1152.f) - mean * mean;
    const float rstd = rsqrtf(var + 1e-5f);
#pragma unroll
    for (int t = 0; t < 9; ++t) {
        int e = tid + t * 128;
        int ch = g * 12 + e / 96;
        g_xn[b * 9216 + g * 1152 + e] = (vals[t] - mean) * rstd * gamma[ch] + beta[ch];
    }
}

// ---- 2) Precompute (stores M^T, N^T tf32-rounded)
__global__ __launch_bounds__(256, 1)
void pre_kernel(const float* __restrict__ Wq, const float* __restrict__ bq,
                const float* __restrict__ Wk, const float* __restrict__ bk,
                const float* __restrict__ Wv, const float* __restrict__ bv,
                const float* __restrict__ Wo, const float* __restrict__ bo) {
    const int h = blockIdx.x, m = blockIdx.y, tid = threadIdx.x;
    extern __shared__ float sm[];
    float* bufA = sm;
    float* bufB = sm + 9216;
    const float inv = rsqrtf(96.0f);
    const int tx = tid & 15, ty = tid >> 4;
    const int i0 = ty * 6, j0 = tx * 6;

    if (m == 0) {
        for (int idx = tid; idx < 9216; idx += 256) {
            int i = idx / 96, d = idx % 96;
            bufA[idx]        = Wq[i * 768 + h * 96 + d];
            bufB[d * TP + i] = Wk[i * 768 + h * 96 + d];
        }
        __syncthreads();
        ull acc[6][3];
#pragma unroll
        for (int i = 0; i < 6; ++i) for (int p = 0; p < 3; ++p) acc[i][p] = 0ULL;
        gemm96<1, TP>(bufA, bufB, i0, j0, acc);   // M = Wq_h Wk_h^T
#pragma unroll
        for (int i = 0; i < 6; ++i)
#pragma unroll
            for (int p = 0; p < 3; ++p) {
                float2 f = unpk(acc[i][p]);
                g_M[h * 9216 + (j0 + 2 * p)     * 96 + (i0 + i)] = __uint_as_float(f2tf(f.x * inv));
                g_M[h * 9216 + (j0 + 2 * p + 1) * 96 + (i0 + i)] = __uint_as_float(f2tf(f.y * inv));
            }
        if (tid < 96) {
            float a = 0.f, c = 0.f;
            for (int d = 0; d < 96; ++d) {
                a += bufA[tid * 96 + d] * bk[h * 96 + d];
                c += bufB[d * TP + tid] * bq[h * 96 + d];
            }
            g_u[h * 96 + tid] = a * inv;
            g_w[h * 96 + tid] = c * inv;
        }
        if (tid == 0) {
            float cs = 0.f;
            for (int d = 0; d < 96; ++d) cs += bq[h * 96 + d] * bk[h * 96 + d];
            g_cc[h] = cs * inv;
        }
        if (h == 0 && tid >= 128 && tid < 224) {
            int c = tid - 128;
            float s = bo[c];
            for (int j = 0; j < 768; ++j) s += bv[j] * Wo[j * 96 + c];
            g_bp[c] = s;
        }
    } else {
        for (int idx = tid; idx < 9216; idx += 256) {
            int i = idx / 96, d = idx % 96;
            bufA[idx] = Wv[i * 768 + h * 96 + d];
            bufB[idx] = Wo[h * 9216 + idx];
        }
        __syncthreads();
        ull acc[6][3];
#pragma unroll
        for (int i = 0; i < 6; ++i) for (int p = 0; p < 3; ++p) acc[i][p] = 0ULL;
        gemm96<1, 96>(bufA, bufB, i0, j0, acc);   // N = Wv_h Wo_h
#pragma unroll
        for (int i = 0; i < 6; ++i)
#pragma unroll
            for (int p = 0; p < 3; ++p) {
                float2 f = unpk(acc[i][p]);
                g_N[h * 9216 + (j0 + 2 * p)     * 96 + (i0 + i)] = __uint_as_float(f2tf(f.x));
                g_N[h * 9216 + (j0 + 2 * p + 1) * 96 + (i0 + i)] = __uint_as_float(f2tf(f.y));
            }
    }
}

// ---- 3) Attention via tf32 mma.sync, occ=2 (R10 verbatim)
__global__ __launch_bounds__(384, 2)
void attn_kernel() {
    const int b = blockIdx.x, h = blockIdx.y;
    extern __shared__ uint32 smu[];
    uint32* tS = smu;              // t (tf32), later X2^T ; pads: rv,zv,uv,wv
    uint32* W  = smu + 96 * PT;    // M^T, later P        ; pads: pmx,psm
    uint32* Y  = smu + 2 * 96 * PT;// X1, later N^T
    float* tSf = (float*)tS;
    float* Wf  = (float*)W;
#define RV(i)      tSf[(i) * PT + 96]
#define ZV(i)      tSf[(i) * PT + 97]
#define UV(i)      tSf[(i) * PT + 98]
#define WV(i)      tSf[(i) * PT + 99]
#define PMX(hf, i) Wf[(i) * PT + 96 + (hf)]
#define PSM(hf, i) Wf[(i) * PT + 98 + (hf)]

    const int tid = threadIdx.x;
    const int lane = tid & 31, wid = tid >> 5;
    const int r0 = (wid >> 1) * 16, c0 = (wid & 1) * 48;
    const int g = lane >> 2, tg = lane & 3;
    const float NEGINF = __int_as_float(0xff800000);

    {
        const float4* xb4 = (const float4*)(g_xn + b * 9216);
        const float4* Mh4 = (const float4*)(g_M + h * 9216);
#pragma unroll
        for (int r = 0; r < 6; ++r) {
            int idx = tid + r * 384;
            int rr = idx / 24, q4 = idx - rr * 24;
            float4 xv = xb4[idx];
            uint4 tv = make_uint4(f2tf(xv.x), f2tf(xv.y), f2tf(xv.z), f2tf(xv.w));
            *(uint4*)(tS + rr * PT + q4 * 4) = tv;
            *(float4*)(Wf + rr * PT + q4 * 4) = Mh4[idx];
        }
        if (tid < 96) { UV(tid) = g_u[h * 96 + tid]; WV(tid) = g_w[h * 96 + tid]; }
    }
    __syncthreads();

    if (tid < 96) {
        float a = 0.f;
        for (int c = 0; c < 96; ++c) a += __uint_as_float(tS[tid * PT + c]) * UV(c);
        RV(tid) = a;
    } else if (tid < 192) {
        const int j = tid - 96;
        float a = 0.f;
        for (int c = 0; c < 96; ++c) a += __uint_as_float(tS[j * PT + c]) * WV(c);
        ZV(j) = a;
    }

    {
        float c[6][4];
#pragma unroll
        for (int n = 0; n < 6; ++n) for (int q = 0; q < 4; ++q) c[n][q] = 0.f;
        wgemm(tS, W, r0, c0, lane, c);
#pragma unroll
        for (int n = 0; n < 6; ++n) {
            const int col = c0 + n * 8 + 2 * tg, row = r0 + g;
            Y[row * PT + col]           = f2tf(c[n][0]);
            Y[row * PT + col + 1]       = f2tf(c[n][1]);
            Y[(row + 8) * PT + col]     = f2tf(c[n][2]);
            Y[(row + 8) * PT + col + 1] = f2tf(c[n][3]);
        }
    }
    __syncthreads();   // S0: X1 ready; M^T dead

    float sv[6][4];
    {
#pragma unroll
        for (int n = 0; n < 6; ++n) for (int q = 0; q < 4; ++q) sv[n][q] = 0.f;
        wgemm(Y, tS, r0, c0, lane, sv);
    }
    const int i0r = r0 + g, i1r = r0 + g + 8;
    const float ccv = g_cc[h];
    {
        const float ri0 = RV(i0r) + ccv, ri1 = RV(i1r) + ccv;
        float m0 = NEGINF, m1 = NEGINF;
#pragma unroll
        for (int n = 0; n < 6; ++n) {
            const int j0 = c0 + n * 8 + 2 * tg, j1 = j0 + 1;
            float v00 = (j0 <= i0r) ? sv[n][0] + ri0 + ZV(j0) : NEGINF;
            float v01 = (j1 <= i0r) ? sv[n][1] + ri0 + ZV(j1) : NEGINF;
            float v10 = (j0 <= i1r) ? sv[n][2] + ri1 + ZV(j0) : NEGINF;
            float v11 = (j1 <= i1r) ? sv[n][3] + ri1 + ZV(j1) : NEGINF;
            sv[n][0] = v00; sv[n][1] = v01; sv[n][2] = v10; sv[n][3] = v11;
            m0 = fmaxf(m0, fmaxf(v00, v01));
            m1 = fmaxf(m1, fmaxf(v10, v11));
        }
        m0 = fmaxf(m0, __shfl_xor_sync(0xffffffffu, m0, 1));
        m0 = fmaxf(m0, __shfl_xor_sync(0xffffffffu, m0, 2));
        m1 = fmaxf(m1, __shfl_xor_sync(0xffffffffu, m1, 1));
        m1 = fmaxf(m1, __shfl_xor_sync(0xffffffffu, m1, 2));
        if (tg == 0) { PMX(wid & 1, i0r) = m0; PMX(wid & 1, i1r) = m1; }
    }
    __syncthreads();   // S1

    {
        const float m0f = fmaxf(PMX(0, i0r), PMX(1, i0r));
        const float m1f = fmaxf(PMX(0, i1r), PMX(1, i1r));
        float s0 = 0.f, s1 = 0.f;
#pragma unroll
        for (int n = 0; n < 6; ++n) {
            float e0 = __expf(sv[n][0] - m0f), e1 = __expf(sv[n][1] - m0f);
            float e2 = __expf(sv[n][2] - m1f), e3 = __expf(sv[n][3] - m1f);
            sv[n][0] = e0; sv[n][1] = e1; sv[n][2] = e2; sv[n][3] = e3;
            s0 += e0 + e1; s1 += e2 + e3;
        }
        s0 += __shfl_xor_sync(0xffffffffu, s0, 1);
        s0 += __shfl_xor_sync(0xffffffffu, s0, 2);
        s1 += __shfl_xor_sync(0xffffffffu, s1, 1);
        s1 += __shfl_xor_sync(0xffffffffu, s1, 2);
        if (tg == 0) { PSM(wid & 1, i0r) = s0; PSM(wid & 1, i1r) = s1; }
    }
    // stage N^T into Y (pre-rounded copy)
    {
        const float4* Nh4 = (const float4*)(g_N + h * 9216);
        float* Yf = (float*)Y;
#pragma unroll
        for (int r = 0; r < 6; ++r) {
            int idx = tid + r * 384;
            int rr = idx / 24, q4 = idx - rr * 24;
            *(float4*)(Yf + rr * PT + q4 * 4) = Nh4[idx];
        }
    }
    __syncthreads();   // S2: sums + N^T ready

    {
        const float is0 = 1.0f / (PSM(0, i0r) + PSM(1, i0r));
        const float is1 = 1.0f / (PSM(0, i1r) + PSM(1, i1r));
#pragma unroll
        for (int n = 0; n < 6; ++n) {
            const int col = c0 + n * 8 + 2 * tg;
            W[i0r * PT + col]     = f2tf(sv[n][0] * is0);
            W[i0r * PT + col + 1] = f2tf(sv[n][1] * is0);
            W[i1r * PT + col]     = f2tf(sv[n][2] * is1);
            W[i1r * PT + col + 1] = f2tf(sv[n][3] * is1);
        }
    }

    {
        float c[6][4];
#pragma unroll
        for (int n = 0; n < 6; ++n) for (int q = 0; q < 4; ++q) c[n][q] = 0.f;
        wgemm(tS, Y, r0, c0, lane, c);
        __syncthreads();   // S3
#pragma unroll
        for (int n = 0; n < 6; ++n) {
            const int col = c0 + n * 8 + 2 * tg, row = r0 + g;
            tS[col * PT + row]           = f2tf(c[n][0]);
            tS[(col + 1) * PT + row]     = f2tf(c[n][1]);
            tS[col * PT + row + 8]       = f2tf(c[n][2]);
            tS[(col + 1) * PT + row + 8] = f2tf(c[n][3]);
        }
    }
    __syncthreads();   // S4: X2^T ready

    {
        float c[6][4];
#pragma unroll
        for (int n = 0; n < 6; ++n) for (int q = 0; q < 4; ++q) c[n][q] = 0.f;
        wgemm(W, tS, r0, c0, lane, c);
        float* dst = g_part + (h * 96 + b) * 9216;
#pragma unroll
        for (int n = 0; n < 6; ++n) {
            const int l0 = c0 + n * 8 + 2 * tg, row = r0 + g;
            *(float2*)(dst + row * 96 + l0)       = make_float2(c[n][0], c[n][1]);
            *(float2*)(dst + (row + 8) * 96 + l0) = make_float2(c[n][2], c[n][3]);
        }
    }
#undef RV
#undef ZV
#undef UV
#undef WV
#undef PMX
#undef PSM
}

// ---- 4) Head reduction + bias
__global__ void reduce_kernel() {
    const int idx = blockIdx.x * 256 + threadIdx.x;
    float4 a = ((const float4*)g_bp)[idx % 24];
#pragma unroll
    for (int h = 0; h < 8; ++h) {
        float4 p = ((const float4*)g_part)[h * 221184 + idx];
        a.x += p.x; a.y += p.y; a.z += p.z; a.w += p.w;
    }
    ((float4*)g_O)[idx] = a;
}

// ---- 5) Broadcast residual, s-split for occupancy:
// grid (6 bt, 96 j, 2 sh), 384 thr; block stores 16 b x 48 s x 96 l.
__global__ __launch_bounds__(384)
void bcast_kernel(float* __restrict__ out) {
    __shared__ __align__(16) float O_s[4608];   // 48 rows x 96
    const int bt = blockIdx.x, j = blockIdx.y, sh = blockIdx.z;
    const int tid = threadIdx.x;
    const float4* Og = (const float4*)(g_O + j * 9216 + sh * 48 * 96);
    float4* Os4 = (float4*)O_s;
#pragma unroll
    for (int r = 0; r < 3; ++r) Os4[tid + r * 384] = Og[tid + r * 384];
    const int b_i = tid / 24;       // 0..15
    const int q   = tid - b_i * 24; // 0..23
    const int bg  = bt * 16 + b_i;
    const float4 xnv = *(const float4*)(g_xn + (size_t)bg * 9216 + j * 96 + q * 4);
    __syncthreads();
    float* dst = out + ((size_t)bg * 96 + (size_t)j) * 9216 + (size_t)(sh * 48) * 96 + q * 4;
#pragma unroll 8
    for (int s = 0; s < 48; ++s) {
        float4 o = Os4[s * 24 + q];
        float4 v = make_float4(o.x + xnv.x, o.y + xnv.y, o.z + xnv.z, o.w + xnv.w);
        __stcs((float4*)(dst + s * 96), v);
    }
}

extern "C" void kernel_launch(void* const* d_in, const int* in_sizes, int n_in,
                              void* d_out, int out_size) {
    const float* x     = (const float*)d_in[0];
    const float* Wq    = (const float*)d_in[1];
    const float* bq    = (const float*)d_in[2];
    const float* Wk    = (const float*)d_in[3];
    const float* bk    = (const float*)d_in[4];
    const float* Wv    = (const float*)d_in[5];
    const float* bv    = (const float*)d_in[6];
    const float* Wo    = (const float*)d_in[7];
    const float* bo    = (const float*)d_in[8];
    const float* gamma = (const float*)d_in[9];
    const float* beta  = (const float*)d_in[10];
    float* out = (float*)d_out;

    const int pre_smem  = (9216 + 96 * TP) * 4;
    const int attn_smem = 3 * 96 * PT * 4;   // 115,200 B -> 2 CTAs/SM
    cudaFuncSetAttribute(pre_kernel,  cudaFuncAttributeMaxDynamicSharedMemorySize, pre_smem);
    cudaFuncSetAttribute(attn_kernel, cudaFuncAttributeMaxDynamicSharedMemorySize, attn_smem);

    gn_kernel<<<dim3(96, 8), 128>>>(x, gamma, beta);
    pre_kernel<<<dim3(8, 2), 256, pre_smem>>>(Wq, bq, Wk, bk, Wv, bv, Wo, bo);
    attn_kernel<<<dim3(96, 8), 384, attn_smem>>>();
    reduce_kernel<<<864, 256>>>();
    bcast_kernel<<<dim3(6, 96, 2), 384>>>(out);
}

// round 15
// speedup vs baseline: 1.1917x; 1.1596x over previous
#include <cuda_runtime.h>
#include <cuda_bf16.h>
#include <math.h>

#define TP 98
#define PB 52            // bf16x2 buffer pitch in words (52 mod 32 = 20 -> conflict-free)
typedef unsigned long long ull;
typedef unsigned uint32;

__device__ __align__(16) float  g_xn[96*96*96];
__device__ __align__(16) uint32 g_M[8*96*48];   // M~^T bf16x2 packed: [h][j][c/2]
__device__ __align__(16) uint32 g_N[8*96*48];   // N^T  bf16x2 packed: [h][l][c/2]
__device__ __align__(16) float  g_u[8*96];
__device__ __align__(16) float  g_w[8*96];
__device__ __align__(16) float  g_cc[8];
__device__ __align__(16) float  g_bp[96];
__device__ __align__(16) float  g_part[8*96*96*96];
__device__ __align__(16) float  g_O[96*96*96];

__device__ __forceinline__ ull pack2(float a) {
    ull r; asm("mov.b64 %0, {%1, %2};" : "=l"(r) : "f"(a), "f"(a)); return r;
}
__device__ __forceinline__ ull fma2(ull a, ull b, ull c) {
    ull d; asm("fma.rn.f32x2 %0, %1, %2, %3;" : "=l"(d) : "l"(a), "l"(b), "l"(c)); return d;
}
__device__ __forceinline__ float2 unpk(ull p) {
    float2 f; asm("mov.b64 {%0, %1}, %2;" : "=f"(f.x), "=f"(f.y) : "l"(p)); return f;
}
__device__ __forceinline__ uint32 f2bf2(float lo, float hi) {
    __nv_bfloat162 h = __floats2bfloat162_rn(lo, hi);
    return *reinterpret_cast<uint32*>(&h);
}
__device__ __forceinline__ float2 bf2f(uint32 w) {
    __nv_bfloat162 h = *reinterpret_cast<__nv_bfloat162*>(&w);
    return __bfloat1622float2(h);
}
__device__ __forceinline__ void mma16(float c[4], uint32 a0, uint32 a1, uint32 a2, uint32 a3,
                                      uint32 b0, uint32 b1) {
    asm("mma.sync.aligned.m16n8k16.row.col.f32.bf16.bf16.f32 "
        "{%0,%1,%2,%3},{%4,%5,%6,%7},{%8,%9},{%0,%1,%2,%3};"
        : "+f"(c[0]), "+f"(c[1]), "+f"(c[2]), "+f"(c[3])
        : "r"(a0), "r"(a1), "r"(a2), "r"(a3), "r"(b0), "r"(b1));
}

// Warp GEMM: C(16x96) = A(rows r0..r0+15, k 0..95) x B([n][k], bf16x2 packed, pitch PB)
__device__ __forceinline__ void wgemm12(const uint32* __restrict__ A,
                                        const uint32* __restrict__ B,
                                        int r0, int lane, float c[12][4]) {
    const int g = lane >> 2, tg = lane & 3;
    const uint32* Ap = A + (r0 + g) * PB + tg;
    const uint32* Bp = B + g * PB + tg;
#pragma unroll
    for (int ks = 0; ks < 6; ++ks) {
        const int kb = ks * 8;
        uint32 a0 = Ap[kb], a1 = Ap[8 * PB + kb], a2 = Ap[kb + 4], a3 = Ap[8 * PB + kb + 4];
#pragma unroll
        for (int n = 0; n < 12; ++n) {
            uint32 b0 = Bp[n * 8 * PB + kb], b1 = Bp[n * 8 * PB + kb + 4];
            mma16(c[n], a0, a1, a2, a3, b0, b1);
        }
    }
}

// FFMA2 GEMM for pre
template<int AMODE, int PPB>
__device__ __forceinline__ void gemm96(const float* __restrict__ A,
                                       const float* __restrict__ B,
                                       int i0, int j0, ull acc[6][3]) {
    const float* Bj = B + j0;
#pragma unroll 2
    for (int k = 0; k < 96; k += 2) {
        ull b0[3], b1[3];
#pragma unroll
        for (int p = 0; p < 3; ++p) {
            b0[p] = *(const ull*)(Bj + k * PPB + 2 * p);
            b1[p] = *(const ull*)(Bj + (k + 1) * PPB + 2 * p);
        }
        ull a0[6], a1[6];
        if (AMODE == 0) {
#pragma unroll
            for (int ii = 0; ii < 3; ++ii) {
                float2 f0 = *(const float2*)(A + k * TP + i0 + 2 * ii);
                float2 f1 = *(const float2*)(A + (k + 1) * TP + i0 + 2 * ii);
                a0[2*ii] = pack2(f0.x); a0[2*ii+1] = pack2(f0.y);
                a1[2*ii] = pack2(f1.x); a1[2*ii+1] = pack2(f1.y);
            }
        } else {
#pragma unroll
            for (int i = 0; i < 6; ++i) {
                float2 f = *(const float2*)(A + (i0 + i) * 96 + k);
                a0[i] = pack2(f.x); a1[i] = pack2(f.y);
            }
        }
#pragma unroll
        for (int i = 0; i < 6; ++i)
#pragma unroll
            for (int p = 0; p < 3; ++p)
                acc[i][p] = fma2(a0[i], b0[p], acc[i][p]);
#pragma unroll
        for (int i = 0; i < 6; ++i)
#pragma unroll
            for (int p = 0; p < 3; ++p)
                acc[i][p] = fma2(a1[i], b1[p], acc[i][p]);
    }
}

// ---- 1) GroupNorm
__global__ void gn_kernel(const float* __restrict__ x,
                          const float* __restrict__ gamma,
                          const float* __restrict__ beta) {
    const int b = blockIdx.x, g = blockIdx.y, tid = threadIdx.x;
    const float* xp = x + b * 9216 + g * 1152;
    float vals[9], sum = 0.f, sq = 0.f;
#pragma unroll
    for (int t = 0; t < 9; ++t) {
        float v = xp[tid + t * 128];
        vals[t] = v; sum += v; sq += v * v;
    }
    __shared__ float s1[128], s2[128];
    s1[tid] = sum; s2[tid] = sq;
    __syncthreads();
    for (int o = 64; o > 0; o >>= 1) {
        if (tid < o) { s1[tid] += s1[tid + o]; s2[tid] += s2[tid + o]; }
        __syncthreads();
    }
    const float mean = s1[0] * (1.f / 1152.f);
    const float var  = s2[0] * (1.f / 1152.f) - mean * mean;
    const float rstd = rsqrtf(var + 1e-5f);
#pragma unroll
    for (int t = 0; t < 9; ++t) {
        int e = tid + t * 128;
        int ch = g * 12 + e / 96;
        g_xn[b * 9216 + g * 1152 + e] = (vals[t] - mean) * rstd * gamma[ch] + beta[ch];
    }
}

// ---- 2) Precompute (stores M^T, N^T packed bf16x2 along c)
__global__ __launch_bounds__(256, 1)
void pre_kernel(const float* __restrict__ Wq, const float* __restrict__ bq,
                const float* __restrict__ Wk, const float* __restrict__ bk,
                const float* __restrict__ Wv, const float* __restrict__ bv,
                const float* __restrict__ Wo, const float* __restrict__ bo) {
    const int h = blockIdx.x, m = blockIdx.y, tid = threadIdx.x;
    extern __shared__ float sm[];
    float* bufA = sm;
    float* bufB = sm + 9216;
    const float inv = rsqrtf(96.0f);
    const int tx = tid & 15, ty = tid >> 4;
    const int i0 = ty * 6, j0 = tx * 6;

    if (m == 0) {
        for (int idx = tid; idx < 9216; idx += 256) {
            int i = idx / 96, d = idx % 96;
            bufA[idx]        = Wq[i * 768 + h * 96 + d];
            bufB[d * TP + i] = Wk[i * 768 + h * 96 + d];
        }
        __syncthreads();
        ull acc[6][3];
#pragma unroll
        for (int i = 0; i < 6; ++i) for (int p = 0; p < 3; ++p) acc[i][p] = 0ULL;
        gemm96<1, TP>(bufA, bufB, i0, j0, acc);   // M = Wq_h Wk_h^T
        float mv[6][6];
#pragma unroll
        for (int i = 0; i < 6; ++i)
#pragma unroll
            for (int p = 0; p < 3; ++p) {
                float2 f = unpk(acc[i][p]);
                mv[i][2 * p] = f.x * inv; mv[i][2 * p + 1] = f.y * inv;
            }
#pragma unroll
        for (int s = 0; s < 3; ++s)
#pragma unroll
            for (int jj = 0; jj < 6; ++jj)
                g_M[h * 4608 + (j0 + jj) * 48 + (i0 >> 1) + s] =
                    f2bf2(mv[2 * s][jj], mv[2 * s + 1][jj]);
        if (tid < 96) {
            float a = 0.f, c = 0.f;
            for (int d = 0; d < 96; ++d) {
                a += bufA[tid * 96 + d] * bk[h * 96 + d];
                c += bufB[d * TP + tid] * bq[h * 96 + d];
            }
            g_u[h * 96 + tid] = a * inv;
            g_w[h * 96 + tid] = c * inv;
        }
        if (tid == 0) {
            float cs = 0.f;
            for (int d = 0; d < 96; ++d) cs += bq[h * 96 + d] * bk[h * 96 + d];
            g_cc[h] = cs * inv;
        }
        if (h == 0 && tid >= 128 && tid < 224) {
            int c = tid - 128;
            float s = bo[c];
            for (int j = 0; j < 768; ++j) s += bv[j] * Wo[j * 96 + c];
            g_bp[c] = s;
        }
    } else {
        for (int idx = tid; idx < 9216; idx += 256) {
            int i = idx / 96, d = idx % 96;
            bufA[idx] = Wv[i * 768 + h * 96 + d];
            bufB[idx] = Wo[h * 9216 + idx];
        }
        __syncthreads();
        ull acc[6][3];
#pragma unroll
        for (int i = 0; i < 6; ++i) for (int p = 0; p < 3; ++p) acc[i][p] = 0ULL;
        gemm96<1, 96>(bufA, bufB, i0, j0, acc);   // N = Wv_h Wo_h
        float mv[6][6];
#pragma unroll
        for (int i = 0; i < 6; ++i)
#pragma unroll
            for (int p = 0; p < 3; ++p) {
                float2 f = unpk(acc[i][p]);
                mv[i][2 * p] = f.x; mv[i][2 * p + 1] = f.y;
            }
#pragma unroll
        for (int s = 0; s < 3; ++s)
#pragma unroll
            for (int jj = 0; jj < 6; ++jj)
                g_N[h * 4608 + (j0 + jj) * 48 + (i0 >> 1) + s] =
                    f2bf2(mv[2 * s][jj], mv[2 * s + 1][jj]);
    }
}

// ---- 3) Attention: bf16 m16n8k16 mma, 6 warps x (16 x 96) tiles, occ=3
__global__ __launch_bounds__(192, 3)
void attn_kernel() {
    const int b = blockIdx.x, h = blockIdx.y;
    extern __shared__ uint32 smu[];
    uint32* tS = smu;             // t(bf16x2) -> X2^T ; pads 48=UV,49=WV,50=RV,51=ZV (fp32)
    uint32* W  = smu + 96 * PB;   // M^T -> N^T
    uint32* Y  = smu + 2 * 96 * PB;// X1 -> P
    float* tSf = (float*)tS;

    const int tid = threadIdx.x;
    const int lane = tid & 31, wid = tid >> 5;  // 6 warps
    const int r0 = wid * 16;
    const int g = lane >> 2, tg = lane & 3;
    const float NEGINF = __int_as_float(0xff800000);

    // stage t (fp32 -> bf16x2) and M^T (packed copy)
    {
        const float4* xb4 = (const float4*)(g_xn + b * 9216);
        const uint4*  Mh4 = (const uint4*)(g_M + h * 4608);
#pragma unroll
        for (int r = 0; r < 6; ++r) {
            int idx = tid + r * 192;          // 0..1151 (uint4 granules)
            int rr = idx / 12, o = idx - rr * 12;
            float4 v0 = xb4[rr * 24 + 2 * o];
            float4 v1 = xb4[rr * 24 + 2 * o + 1];
            uint4 wv;
            wv.x = f2bf2(v0.x, v0.y); wv.y = f2bf2(v0.z, v0.w);
            wv.z = f2bf2(v1.x, v1.y); wv.w = f2bf2(v1.z, v1.w);
            *(uint4*)(tS + rr * PB + o * 4) = wv;
            *(uint4*)(W  + rr * PB + o * 4) = Mh4[idx];
        }
        if (tid < 96) { tSf[tid * PB + 48] = g_u[h * 96 + tid];
                        tSf[tid * PB + 49] = g_w[h * 96 + tid]; }
    }
    __syncthreads();   // A

    // r (threads 0..95), z (96..191)
    if (tid < 96) {
        float a = 0.f;
        for (int w = 0; w < 48; ++w) {
            float2 t2 = bf2f(tS[tid * PB + w]);
            a += t2.x * tSf[(2 * w) * PB + 48] + t2.y * tSf[(2 * w + 1) * PB + 48];
        }
        tSf[tid * PB + 50] = a;                       // RV
    } else {
        const int j = tid - 96;
        float a = 0.f;
        for (int w = 0; w < 48; ++w) {
            float2 t2 = bf2f(tS[j * PB + w]);
            a += t2.x * tSf[(2 * w) * PB + 49] + t2.y * tSf[(2 * w + 1) * PB + 49];
        }
        tSf[j * PB + 51] = a;                         // ZV
    }

    // GEMM1: X1 = t * M  (A=tS, B=W[M^T]) -> Y (bf16x2)
    {
        float c[12][4];
#pragma unroll
        for (int n = 0; n < 12; ++n) for (int q = 0; q < 4; ++q) c[n][q] = 0.f;
        wgemm12(tS, W, r0, lane, c);
#pragma unroll
        for (int n = 0; n < 12; ++n) {
            const int wcol = n * 4 + tg, row = r0 + g;
            Y[row * PB + wcol]       = f2bf2(c[n][0], c[n][1]);
            Y[(row + 8) * PB + wcol] = f2bf2(c[n][2], c[n][3]);
        }
    }
    __syncthreads();   // B: X1 ready; M^T dead

    // prefetch N^T into registers (STS after GEMM2)
    uint4 nreg[6];
    {
        const uint4* Nh4 = (const uint4*)(g_N + h * 4608);
#pragma unroll
        for (int r = 0; r < 6; ++r) nreg[r] = Nh4[tid + r * 192];
    }

    // GEMM2: S = X1 * t^T (A=Y, B=tS) + fully warp-local causal softmax
    {
        float sv[12][4];
#pragma unroll
        for (int n = 0; n < 12; ++n) for (int q = 0; q < 4; ++q) sv[n][q] = 0.f;
        wgemm12(Y, tS, r0, lane, sv);

        const int i0r = r0 + g, i1r = r0 + g + 8;
        const float ccv = g_cc[h];
        const float ri0 = tSf[i0r * PB + 50] + ccv;
        const float ri1 = tSf[i1r * PB + 50] + ccv;
        float m0 = NEGINF, m1 = NEGINF;
#pragma unroll
        for (int n = 0; n < 12; ++n) {
            const int j0 = n * 8 + 2 * tg, j1 = j0 + 1;
            const float z0 = tSf[j0 * PB + 51], z1 = tSf[j1 * PB + 51];
            float v00 = (j0 <= i0r) ? sv[n][0] + ri0 + z0 : NEGINF;
            float v01 = (j1 <= i0r) ? sv[n][1] + ri0 + z1 : NEGINF;
            float v10 = (j0 <= i1r) ? sv[n][2] + ri1 + z0 : NEGINF;
            float v11 = (j1 <= i1r) ? sv[n][3] + ri1 + z1 : NEGINF;
            sv[n][0] = v00; sv[n][1] = v01; sv[n][2] = v10; sv[n][3] = v11;
            m0 = fmaxf(m0, fmaxf(v00, v01));
            m1 = fmaxf(m1, fmaxf(v10, v11));
        }
        m0 = fmaxf(m0, __shfl_xor_sync(0xffffffffu, m0, 1));
        m0 = fmaxf(m0, __shfl_xor_sync(0xffffffffu, m0, 2));
        m1 = fmaxf(m1, __shfl_xor_sync(0xffffffffu, m1, 1));
        m1 = fmaxf(m1, __shfl_xor_sync(0xffffffffu, m1, 2));
        float s0 = 0.f, s1 = 0.f;
#pragma unroll
        for (int n = 0; n < 12; ++n) {
            float e0 = __expf(sv[n][0] - m0), e1 = __expf(sv[n][1] - m0);
            float e2 = __expf(sv[n][2] - m1), e3 = __expf(sv[n][3] - m1);
            sv[n][0] = e0; sv[n][1] = e1; sv[n][2] = e2; sv[n][3] = e3;
            s0 += e0 + e1; s1 += e2 + e3;
        }
        s0 += __shfl_xor_sync(0xffffffffu, s0, 1);
        s0 += __shfl_xor_sync(0xffffffffu, s0, 2);
        s1 += __shfl_xor_sync(0xffffffffu, s1, 1);
        s1 += __shfl_xor_sync(0xffffffffu, s1, 2);
        const float is0 = 1.0f / s0, is1 = 1.0f / s1;
        // P into Y (own rows: no sync needed)
#pragma unroll
        for (int n = 0; n < 12; ++n) {
            const int wcol = n * 4 + tg;
            Y[i0r * PB + wcol] = f2bf2(sv[n][0] * is0, sv[n][1] * is0);
            Y[i1r * PB + wcol] = f2bf2(sv[n][2] * is1, sv[n][3] * is1);
        }
    }

    // store prefetched N^T into W
#pragma unroll
    for (int r = 0; r < 6; ++r) {
        int idx = tid + r * 192;
        int rr = idx / 12, o = idx - rr * 12;
        *(uint4*)(W + rr * PB + o * 4) = nreg[r];
    }
    __syncthreads();   // C: P + N^T ready

    // GEMM3': X2^T = N^T * t^T-form (A=W rows l, B=tS rows s) -> X2^T[l][s]
    {
        float c[12][4];
#pragma unroll
        for (int n = 0; n < 12; ++n) for (int q = 0; q < 4; ++q) c[n][q] = 0.f;
        wgemm12(W, tS, r0, lane, c);
        __syncthreads();   // D: all t reads done
#pragma unroll
        for (int n = 0; n < 12; ++n) {
            const int wcol = n * 4 + tg, row = r0 + g;   // row = l, cols = s
            tS[row * PB + wcol]       = f2bf2(c[n][0], c[n][1]);
            tS[(row + 8) * PB + wcol] = f2bf2(c[n][2], c[n][3]);
        }
    }
    __syncthreads();   // E: X2^T ready

    // GEMM4: AV = P * X2  (A=Y[P] rows s, B=tS[X2^T] rows l) -> g_part fp32
    {
        float c[12][4];
#pragma unroll
        for (int n = 0; n < 12; ++n) for (int q = 0; q < 4; ++q) c[n][q] = 0.f;
        wgemm12(Y, tS, r0, lane, c);
        float* dst = g_part + (h * 96 + b) * 9216;
#pragma unroll
        for (int n = 0; n < 12; ++n) {
            const int l0 = n * 8 + 2 * tg, row = r0 + g;
            *(float2*)(dst + row * 96 + l0)       = make_float2(c[n][0], c[n][1]);
            *(float2*)(dst + (row + 8) * 96 + l0) = make_float2(c[n][2], c[n][3]);
        }
    }
}

// ---- 4) Head reduction + bias
__global__ void reduce_kernel() {
    const int idx = blockIdx.x * 256 + threadIdx.x;
    float4 a = ((const float4*)g_bp)[idx % 24];
#pragma unroll
    for (int h = 0; h < 8; ++h) {
        float4 p = ((const float4*)g_part)[h * 221184 + idx];
        a.x += p.x; a.y += p.y; a.z += p.z; a.w += p.w;
    }
    ((float4*)g_O)[idx] = a;
}

// ---- 5) Broadcast residual, s-split
__global__ __launch_bounds__(384)
void bcast_kernel(float* __restrict__ out) {
    __shared__ __align__(16) float O_s[4608];
    const int bt = blockIdx.x, j = blockIdx.y, sh = blockIdx.z;
    const int tid = threadIdx.x;
    const float4* Og = (const float4*)(g_O + j * 9216 + sh * 48 * 96);
    float4* Os4 = (float4*)O_s;
#pragma unroll
    for (int r = 0; r < 3; ++r) Os4[tid + r * 384] = Og[tid + r * 384];
    const int b_i = tid / 24;
    const int q   = tid - b_i * 24;
    const int bg  = bt * 16 + b_i;
    const float4 xnv = *(const float4*)(g_xn + (size_t)bg * 9216 + j * 96 + q * 4);
    __syncthreads();
    float* dst = out + ((size_t)bg * 96 + (size_t)j) * 9216 + (size_t)(sh * 48) * 96 + q * 4;
#pragma unroll 8
    for (int s = 0; s < 48; ++s) {
        float4 o = Os4[s * 24 + q];
        float4 v = make_float4(o.x + xnv.x, o.y + xnv.y, o.z + xnv.z, o.w + xnv.w);
        __stcs((float4*)(dst + s * 96), v);
    }
}

extern "C" void kernel_launch(void* const* d_in, const int* in_sizes, int n_in,
                              void* d_out, int out_size) {
    const float* x     = (const float*)d_in[0];
    const float* Wq    = (const float*)d_in[1];
    const float* bq    = (const float*)d_in[2];
    const float* Wk    = (const float*)d_in[3];
    const float* bk    = (const float*)d_in[4];
    const float* Wv    = (const float*)d_in[5];
    const float* bv    = (const float*)d_in[6];
    const float* Wo    = (const float*)d_in[7];
    const float* bo    = (const float*)d_in[8];
    const float* gamma = (const float*)d_in[9];
    const float* beta  = (const float*)d_in[10];
    float* out = (float*)d_out;

    const int pre_smem  = (9216 + 96 * TP) * 4;
    const int attn_smem = 3 * 96 * PB * 4;   // 59,904 B -> 3 CTAs/SM
    cudaFuncSetAttribute(pre_kernel,  cudaFuncAttributeMaxDynamicSharedMemorySize, pre_smem);
    cudaFuncSetAttribute(attn_kernel, cudaFuncAttributeMaxDynamicSharedMemorySize, attn_smem);

    gn_kernel<<<dim3(96, 8), 128>>>(x, gamma, beta);
    pre_kernel<<<dim3(8, 2), 256, pre_smem>>>(Wq, bq, Wk, bk, Wv, bv, Wo, bo);
    attn_kernel<<<dim3(96, 8), 192, attn_smem>>>();
    reduce_kernel<<<864, 256>>>();
    bcast_kernel<<<dim3(6, 96, 2), 384>>>(out);
}

// round 16
// speedup vs baseline: 1.2026x; 1.0091x over previous
#include <cuda_runtime.h>
#include <cuda_bf16.h>
#include <math.h>

#define TP 98
#define PB 52            // bf16x2 buffer pitch in words (52 mod 32 = 20 -> conflict-free)
typedef unsigned long long ull;
typedef unsigned uint32;

__device__ __align__(16) float  g_xn[96*96*96];
__device__ __align__(16) uint32 g_M[8*96*48];   // M~^T bf16x2 packed: [h][j][c/2]
__device__ __align__(16) uint32 g_N[8*96*48];   // N^T  bf16x2 packed: [h][l][c/2]
__device__ __align__(16) float  g_u[8*96];
__device__ __align__(16) float  g_w[8*96];
__device__ __align__(16) float  g_cc[8];
__device__ __align__(16) float  g_bp[96];
__device__ __align__(16) float  g_part[8*96*96*96];

__device__ __forceinline__ ull pack2(float a) {
    ull r; asm("mov.b64 %0, {%1, %2};" : "=l"(r) : "f"(a), "f"(a)); return r;
}
__device__ __forceinline__ ull fma2(ull a, ull b, ull c) {
    ull d; asm("fma.rn.f32x2 %0, %1, %2, %3;" : "=l"(d) : "l"(a), "l"(b), "l"(c)); return d;
}
__device__ __forceinline__ float2 unpk(ull p) {
    float2 f; asm("mov.b64 {%0, %1}, %2;" : "=f"(f.x), "=f"(f.y) : "l"(p)); return f;
}
__device__ __forceinline__ uint32 f2bf2(float lo, float hi) {
    __nv_bfloat162 h = __floats2bfloat162_rn(lo, hi);
    return *reinterpret_cast<uint32*>(&h);
}
__device__ __forceinline__ float2 bf2f(uint32 w) {
    __nv_bfloat162 h = *reinterpret_cast<__nv_bfloat162*>(&w);
    return __bfloat1622float2(h);
}
__device__ __forceinline__ void mma16(float c[4], uint32 a0, uint32 a1, uint32 a2, uint32 a3,
                                      uint32 b0, uint32 b1) {
    asm("mma.sync.aligned.m16n8k16.row.col.f32.bf16.bf16.f32 "
        "{%0,%1,%2,%3},{%4,%5,%6,%7},{%8,%9},{%0,%1,%2,%3};"
        : "+f"(c[0]), "+f"(c[1]), "+f"(c[2]), "+f"(c[3])
        : "r"(a0), "r"(a1), "r"(a2), "r"(a3), "r"(b0), "r"(b1));
}

// Warp GEMM: C(16x96) = A(rows r0..r0+15, k 0..95) x B([n][k], bf16x2 packed, pitch PB)
__device__ __forceinline__ void wgemm12(const uint32* __restrict__ A,
                                        const uint32* __restrict__ B,
                                        int r0, int lane, float c[12][4]) {
    const int g = lane >> 2, tg = lane & 3;
    const uint32* Ap = A + (r0 + g) * PB + tg;
    const uint32* Bp = B + g * PB + tg;
#pragma unroll
    for (int ks = 0; ks < 6; ++ks) {
        const int kb = ks * 8;
        uint32 a0 = Ap[kb], a1 = Ap[8 * PB + kb], a2 = Ap[kb + 4], a3 = Ap[8 * PB + kb + 4];
#pragma unroll
        for (int n = 0; n < 12; ++n) {
            uint32 b0 = Bp[n * 8 * PB + kb], b1 = Bp[n * 8 * PB + kb + 4];
            mma16(c[n], a0, a1, a2, a3, b0, b1);
        }
    }
}

// FFMA2 GEMM for pre
template<int AMODE, int PPB>
__device__ __forceinline__ void gemm96(const float* __restrict__ A,
                                       const float* __restrict__ B,
                                       int i0, int j0, ull acc[6][3]) {
    const float* Bj = B + j0;
#pragma unroll 2
    for (int k = 0; k < 96; k += 2) {
        ull b0[3], b1[3];
#pragma unroll
        for (int p = 0; p < 3; ++p) {
            b0[p] = *(const ull*)(Bj + k * PPB + 2 * p);
            b1[p] = *(const ull*)(Bj + (k + 1) * PPB + 2 * p);
        }
        ull a0[6], a1[6];
        if (AMODE == 0) {
#pragma unroll
            for (int ii = 0; ii < 3; ++ii) {
                float2 f0 = *(const float2*)(A + k * TP + i0 + 2 * ii);
                float2 f1 = *(const float2*)(A + (k + 1) * TP + i0 + 2 * ii);
                a0[2*ii] = pack2(f0.x); a0[2*ii+1] = pack2(f0.y);
                a1[2*ii] = pack2(f1.x); a1[2*ii+1] = pack2(f1.y);
            }
        } else {
#pragma unroll
            for (int i = 0; i < 6; ++i) {
                float2 f = *(const float2*)(A + (i0 + i) * 96 + k);
                a0[i] = pack2(f.x); a1[i] = pack2(f.y);
            }
        }
#pragma unroll
        for (int i = 0; i < 6; ++i)
#pragma unroll
            for (int p = 0; p < 3; ++p)
                acc[i][p] = fma2(a0[i], b0[p], acc[i][p]);
#pragma unroll
        for (int i = 0; i < 6; ++i)
#pragma unroll
            for (int p = 0; p < 3; ++p)
                acc[i][p] = fma2(a1[i], b1[p], acc[i][p]);
    }
}

// ---- 1) GroupNorm
__global__ void gn_kernel(const float* __restrict__ x,
                          const float* __restrict__ gamma,
                          const float* __restrict__ beta) {
    const int b = blockIdx.x, g = blockIdx.y, tid = threadIdx.x;
    const float* xp = x + b * 9216 + g * 1152;
    float vals[9], sum = 0.f, sq = 0.f;
#pragma unroll
    for (int t = 0; t < 9; ++t) {
        float v = xp[tid + t * 128];
        vals[t] = v; sum += v; sq += v * v;
    }
    __shared__ float s1[128], s2[128];
    s1[tid] = sum; s2[tid] = sq;
    __syncthreads();
    for (int o = 64; o > 0; o >>= 1) {
        if (tid < o) { s1[tid] += s1[tid + o]; s2[tid] += s2[tid + o]; }
        __syncthreads();
    }
    const float mean = s1[0] * (1.f / 1152.f);
    const float var  = s2[0] * (1.f / 1152.f) - mean * mean;
    const float rstd = rsqrtf(var + 1e-5f);
#pragma unroll
    for (int t = 0; t < 9; ++t) {
        int e = tid + t * 128;
        int ch = g * 12 + e / 96;
        g_xn[b * 9216 + g * 1152 + e] = (vals[t] - mean) * rstd * gamma[ch] + beta[ch];
    }
}

// ---- 2) Precompute (stores M^T, N^T packed bf16x2 along c)
__global__ __launch_bounds__(256, 1)
void pre_kernel(const float* __restrict__ Wq, const float* __restrict__ bq,
                const float* __restrict__ Wk, const float* __restrict__ bk,
                const float* __restrict__ Wv, const float* __restrict__ bv,
                const float* __restrict__ Wo, const float* __restrict__ bo) {
    const int h = blockIdx.x, m = blockIdx.y, tid = threadIdx.x;
    extern __shared__ float sm[];
    float* bufA = sm;
    float* bufB = sm + 9216;
    const float inv = rsqrtf(96.0f);
    const int tx = tid & 15, ty = tid >> 4;
    const int i0 = ty * 6, j0 = tx * 6;

    if (m == 0) {
        for (int idx = tid; idx < 9216; idx += 256) {
            int i = idx / 96, d = idx % 96;
            bufA[idx]        = Wq[i * 768 + h * 96 + d];
            bufB[d * TP + i] = Wk[i * 768 + h * 96 + d];
        }
        __syncthreads();
        ull acc[6][3];
#pragma unroll
        for (int i = 0; i < 6; ++i) for (int p = 0; p < 3; ++p) acc[i][p] = 0ULL;
        gemm96<1, TP>(bufA, bufB, i0, j0, acc);   // M = Wq_h Wk_h^T
        float mv[6][6];
#pragma unroll
        for (int i = 0; i < 6; ++i)
#pragma unroll
            for (int p = 0; p < 3; ++p) {
                float2 f = unpk(acc[i][p]);
                mv[i][2 * p] = f.x * inv; mv[i][2 * p + 1] = f.y * inv;
            }
#pragma unroll
        for (int s = 0; s < 3; ++s)
#pragma unroll
            for (int jj = 0; jj < 6; ++jj)
                g_M[h * 4608 + (j0 + jj) * 48 + (i0 >> 1) + s] =
                    f2bf2(mv[2 * s][jj], mv[2 * s + 1][jj]);
        if (tid < 96) {
            float a = 0.f, c = 0.f;
            for (int d = 0; d < 96; ++d) {
                a += bufA[tid * 96 + d] * bk[h * 96 + d];
                c += bufB[d * TP + tid] * bq[h * 96 + d];
            }
            g_u[h * 96 + tid] = a * inv;
            g_w[h * 96 + tid] = c * inv;
        }
        if (tid == 0) {
            float cs = 0.f;
            for (int d = 0; d < 96; ++d) cs += bq[h * 96 + d] * bk[h * 96 + d];
            g_cc[h] = cs * inv;
        }
        if (h == 0 && tid >= 128 && tid < 224) {
            int c = tid - 128;
            float s = bo[c];
            for (int j = 0; j < 768; ++j) s += bv[j] * Wo[j * 96 + c];
            g_bp[c] = s;
        }
    } else {
        for (int idx = tid; idx < 9216; idx += 256) {
            int i = idx / 96, d = idx % 96;
            bufA[idx] = Wv[i * 768 + h * 96 + d];
            bufB[idx] = Wo[h * 9216 + idx];
        }
        __syncthreads();
        ull acc[6][3];
#pragma unroll
        for (int i = 0; i < 6; ++i) for (int p = 0; p < 3; ++p) acc[i][p] = 0ULL;
        gemm96<1, 96>(bufA, bufB, i0, j0, acc);   // N = Wv_h Wo_h
        float mv[6][6];
#pragma unroll
        for (int i = 0; i < 6; ++i)
#pragma unroll
            for (int p = 0; p < 3; ++p) {
                float2 f = unpk(acc[i][p]);
                mv[i][2 * p] = f.x; mv[i][2 * p + 1] = f.y;
            }
#pragma unroll
        for (int s = 0; s < 3; ++s)
#pragma unroll
            for (int jj = 0; jj < 6; ++jj)
                g_N[h * 4608 + (j0 + jj) * 48 + (i0 >> 1) + s] =
                    f2bf2(mv[2 * s][jj], mv[2 * s + 1][jj]);
    }
}

// ---- 3) Attention: bf16 m16n8k16 mma, 6 warps x (16 x 96) tiles, occ=3 (R15 verbatim)
__global__ __launch_bounds__(192, 3)
void attn_kernel() {
    const int b = blockIdx.x, h = blockIdx.y;
    extern __shared__ uint32 smu[];
    uint32* tS = smu;             // t(bf16x2) -> X2^T ; pads 48=UV,49=WV,50=RV,51=ZV (fp32)
    uint32* W  = smu + 96 * PB;   // M^T -> N^T
    uint32* Y  = smu + 2 * 96 * PB;// X1 -> P
    float* tSf = (float*)tS;

    const int tid = threadIdx.x;
    const int lane = tid & 31, wid = tid >> 5;  // 6 warps
    const int r0 = wid * 16;
    const int g = lane >> 2, tg = lane & 3;
    const float NEGINF = __int_as_float(0xff800000);

    {
        const float4* xb4 = (const float4*)(g_xn + b * 9216);
        const uint4*  Mh4 = (const uint4*)(g_M + h * 4608);
#pragma unroll
        for (int r = 0; r < 6; ++r) {
            int idx = tid + r * 192;
            int rr = idx / 12, o = idx - rr * 12;
            float4 v0 = xb4[rr * 24 + 2 * o];
            float4 v1 = xb4[rr * 24 + 2 * o + 1];
            uint4 wv;
            wv.x = f2bf2(v0.x, v0.y); wv.y = f2bf2(v0.z, v0.w);
            wv.z = f2bf2(v1.x, v1.y); wv.w = f2bf2(v1.z, v1.w);
            *(uint4*)(tS + rr * PB + o * 4) = wv;
            *(uint4*)(W  + rr * PB + o * 4) = Mh4[idx];
        }
        if (tid < 96) { tSf[tid * PB + 48] = g_u[h * 96 + tid];
                        tSf[tid * PB + 49] = g_w[h * 96 + tid]; }
    }
    __syncthreads();   // A

    if (tid < 96) {
        float a = 0.f;
        for (int w = 0; w < 48; ++w) {
            float2 t2 = bf2f(tS[tid * PB + w]);
            a += t2.x * tSf[(2 * w) * PB + 48] + t2.y * tSf[(2 * w + 1) * PB + 48];
        }
        tSf[tid * PB + 50] = a;                       // RV
    } else {
        const int j = tid - 96;
        float a = 0.f;
        for (int w = 0; w < 48; ++w) {
            float2 t2 = bf2f(tS[j * PB + w]);
            a += t2.x * tSf[(2 * w) * PB + 49] + t2.y * tSf[(2 * w + 1) * PB + 49];
        }
        tSf[j * PB + 51] = a;                         // ZV
    }

    // GEMM1: X1 = t * M
    {
        float c[12][4];
#pragma unroll
        for (int n = 0; n < 12; ++n) for (int q = 0; q < 4; ++q) c[n][q] = 0.f;
        wgemm12(tS, W, r0, lane, c);
#pragma unroll
        for (int n = 0; n < 12; ++n) {
            const int wcol = n * 4 + tg, row = r0 + g;
            Y[row * PB + wcol]       = f2bf2(c[n][0], c[n][1]);
            Y[(row + 8) * PB + wcol] = f2bf2(c[n][2], c[n][3]);
        }
    }
    __syncthreads();   // B

    uint4 nreg[6];
    {
        const uint4* Nh4 = (const uint4*)(g_N + h * 4608);
#pragma unroll
        for (int r = 0; r < 6; ++r) nreg[r] = Nh4[tid + r * 192];
    }

    // GEMM2 + warp-local causal softmax
    {
        float sv[12][4];
#pragma unroll
        for (int n = 0; n < 12; ++n) for (int q = 0; q < 4; ++q) sv[n][q] = 0.f;
        wgemm12(Y, tS, r0, lane, sv);

        const int i0r = r0 + g, i1r = r0 + g + 8;
        const float ccv = g_cc[h];
        const float ri0 = tSf[i0r * PB + 50] + ccv;
        const float ri1 = tSf[i1r * PB + 50] + ccv;
        float m0 = NEGINF, m1 = NEGINF;
#pragma unroll
        for (int n = 0; n < 12; ++n) {
            const int j0 = n * 8 + 2 * tg, j1 = j0 + 1;
            const float z0 = tSf[j0 * PB + 51], z1 = tSf[j1 * PB + 51];
            float v00 = (j0 <= i0r) ? sv[n][0] + ri0 + z0 : NEGINF;
            float v01 = (j1 <= i0r) ? sv[n][1] + ri0 + z1 : NEGINF;
            float v10 = (j0 <= i1r) ? sv[n][2] + ri1 + z0 : NEGINF;
            float v11 = (j1 <= i1r) ? sv[n][3] + ri1 + z1 : NEGINF;
            sv[n][0] = v00; sv[n][1] = v01; sv[n][2] = v10; sv[n][3] = v11;
            m0 = fmaxf(m0, fmaxf(v00, v01));
            m1 = fmaxf(m1, fmaxf(v10, v11));
        }
        m0 = fmaxf(m0, __shfl_xor_sync(0xffffffffu, m0, 1));
        m0 = fmaxf(m0, __shfl_xor_sync(0xffffffffu, m0, 2));
        m1 = fmaxf(m1, __shfl_xor_sync(0xffffffffu, m1, 1));
        m1 = fmaxf(m1, __shfl_xor_sync(0xffffffffu, m1, 2));
        float s0 = 0.f, s1 = 0.f;
#pragma unroll
        for (int n = 0; n < 12; ++n) {
            float e0 = __expf(sv[n][0] - m0), e1 = __expf(sv[n][1] - m0);
            float e2 = __expf(sv[n][2] - m1), e3 = __expf(sv[n][3] - m1);
            sv[n][0] = e0; sv[n][1] = e1; sv[n][2] = e2; sv[n][3] = e3;
            s0 += e0 + e1; s1 += e2 + e3;
        }
        s0 += __shfl_xor_sync(0xffffffffu, s0, 1);
        s0 += __shfl_xor_sync(0xffffffffu, s0, 2);
        s1 += __shfl_xor_sync(0xffffffffu, s1, 1);
        s1 += __shfl_xor_sync(0xffffffffu, s1, 2);
        const float is0 = 1.0f / s0, is1 = 1.0f / s1;
#pragma unroll
        for (int n = 0; n < 12; ++n) {
            const int wcol = n * 4 + tg;
            Y[i0r * PB + wcol] = f2bf2(sv[n][0] * is0, sv[n][1] * is0);
            Y[i1r * PB + wcol] = f2bf2(sv[n][2] * is1, sv[n][3] * is1);
        }
    }

#pragma unroll
    for (int r = 0; r < 6; ++r) {
        int idx = tid + r * 192;
        int rr = idx / 12, o = idx - rr * 12;
        *(uint4*)(W + rr * PB + o * 4) = nreg[r];
    }
    __syncthreads();   // C

    // GEMM3': X2^T = N^T x t (rows l)
    {
        float c[12][4];
#pragma unroll
        for (int n = 0; n < 12; ++n) for (int q = 0; q < 4; ++q) c[n][q] = 0.f;
        wgemm12(W, tS, r0, lane, c);
        __syncthreads();   // D
#pragma unroll
        for (int n = 0; n < 12; ++n) {
            const int wcol = n * 4 + tg, row = r0 + g;
            tS[row * PB + wcol]       = f2bf2(c[n][0], c[n][1]);
            tS[(row + 8) * PB + wcol] = f2bf2(c[n][2], c[n][3]);
        }
    }
    __syncthreads();   // E

    // GEMM4: AV = P * X2 -> g_part
    {
        float c[12][4];
#pragma unroll
        for (int n = 0; n < 12; ++n) for (int q = 0; q < 4; ++q) c[n][q] = 0.f;
        wgemm12(Y, tS, r0, lane, c);
        float* dst = g_part + (h * 96 + b) * 9216;
#pragma unroll
        for (int n = 0; n < 12; ++n) {
            const int l0 = n * 8 + 2 * tg, row = r0 + g;
            *(float2*)(dst + row * 96 + l0)       = make_float2(c[n][0], c[n][1]);
            *(float2*)(dst + (row + 8) * 96 + l0) = make_float2(c[n][2], c[n][3]);
        }
    }
}

// ---- 4) Fused head-reduce + broadcast, s-split:
// out[b,j,s,l] = sum_h part[h,j,s,l] + bp[l] + xn[b,j,l]
// grid (6 bt, 96 j, 2 sh), 384 thr. Consecutive bt blocks share the part slab -> L2.
__global__ __launch_bounds__(384)
void redbc_kernel(float* __restrict__ out) {
    __shared__ __align__(16) float O_s[4608];   // 48 rows x 96
    const int bt = blockIdx.x, j = blockIdx.y, sh = blockIdx.z;
    const int tid = threadIdx.x;
    float4* Os4 = (float4*)O_s;
    const float4* bp4 = (const float4*)g_bp;
#pragma unroll
    for (int r = 0; r < 3; ++r) {
        int idx = tid + r * 384;                 // 1152 float4s = 48 x 24
        float4 a = bp4[idx % 24];
#pragma unroll
        for (int h = 0; h < 8; ++h) {
            float4 p = ((const float4*)(g_part + (size_t)h * 884736
                                               + (size_t)j * 9216
                                               + (size_t)sh * 4608))[idx];
            a.x += p.x; a.y += p.y; a.z += p.z; a.w += p.w;
        }
        Os4[idx] = a;
    }
    const int b_i = tid / 24;       // 0..15
    const int q   = tid - b_i * 24; // 0..23
    const int bg  = bt * 16 + b_i;
    const float4 xnv = *(const float4*)(g_xn + (size_t)bg * 9216 + j * 96 + q * 4);
    __syncthreads();
    float* dst = out + ((size_t)bg * 96 + (size_t)j) * 9216 + (size_t)(sh * 48) * 96 + q * 4;
#pragma unroll 8
    for (int s = 0; s < 48; ++s) {
        float4 o = Os4[s * 24 + q];
        float4 v = make_float4(o.x + xnv.x, o.y + xnv.y, o.z + xnv.z, o.w + xnv.w);
        __stcs((float4*)(dst + s * 96), v);
    }
}

extern "C" void kernel_launch(void* const* d_in, const int* in_sizes, int n_in,
                              void* d_out, int out_size) {
    const float* x     = (const float*)d_in[0];
    const float* Wq    = (const float*)d_in[1];
    const float* bq    = (const float*)d_in[2];
    const float* Wk    = (const float*)d_in[3];
    const float* bk    = (const float*)d_in[4];
    const float* Wv    = (const float*)d_in[5];
    const float* bv    = (const float*)d_in[6];
    const float* Wo    = (const float*)d_in[7];
    const float* bo    = (const float*)d_in[8];
    const float* gamma = (const float*)d_in[9];
    const float* beta  = (const float*)d_in[10];
    float* out = (float*)d_out;

    const int pre_smem  = (9216 + 96 * TP) * 4;
    const int attn_smem = 3 * 96 * PB * 4;   // 59,904 B -> 3 CTAs/SM
    cudaFuncSetAttribute(pre_kernel,  cudaFuncAttributeMaxDynamicSharedMemorySize, pre_smem);
    cudaFuncSetAttribute(attn_kernel, cudaFuncAttributeMaxDynamicSharedMemorySize, attn_smem);

    gn_kernel<<<dim3(96, 8), 128>>>(x, gamma, beta);
    pre_kernel<<<dim3(8, 2), 256, pre_smem>>>(Wq, bq, Wk, bk, Wv, bv, Wo, bo);
    attn_kernel<<<dim3(96, 8), 192, attn_smem>>>();
    redbc_kernel<<<dim3(6, 96, 2), 384>>>(out);
}

// round 17
// speedup vs baseline: 1.2879x; 1.0709x over previous
#include <cuda_runtime.h>
#include <cuda_bf16.h>
#include <math.h>

#define TP 98
#define PB 52            // bf16x2 buffer pitch in words (52 mod 32 = 20 -> conflict-free)
typedef unsigned long long ull;
typedef unsigned uint32;

__device__ __align__(16) float  g_xn[96*96*96];
__device__ __align__(16) uint32 g_M[8*96*48];   // M~^T bf16x2 packed: [h][j][c/2]
__device__ __align__(16) uint32 g_N[8*96*48];   // N^T  bf16x2 packed: [h][l][c/2]
__device__ __align__(16) float  g_u[8*96];
__device__ __align__(16) float  g_w[8*96];
__device__ __align__(16) float  g_cc[8];
__device__ __align__(16) float  g_bp[96];
__device__ __align__(16) uint32 g_part[8*96*96*48];   // bf16x2 packed partials [h][b][s][l/2]

__device__ __forceinline__ uint32 f2bf2(float lo, float hi) {
    __nv_bfloat162 h = __floats2bfloat162_rn(lo, hi);
    return *reinterpret_cast<uint32*>(&h);
}
__device__ __forceinline__ float2 bf2f(uint32 w) {
    __nv_bfloat162 h = *reinterpret_cast<__nv_bfloat162*>(&w);
    return __bfloat1622float2(h);
}
__device__ __forceinline__ void mma16(float c[4], uint32 a0, uint32 a1, uint32 a2, uint32 a3,
                                      uint32 b0, uint32 b1) {
    asm("mma.sync.aligned.m16n8k16.row.col.f32.bf16.bf16.f32 "
        "{%0,%1,%2,%3},{%4,%5,%6,%7},{%8,%9},{%0,%1,%2,%3};"
        : "+f"(c[0]), "+f"(c[1]), "+f"(c[2]), "+f"(c[3])
        : "r"(a0), "r"(a1), "r"(a2), "r"(a3), "r"(b0), "r"(b1));
}

// Warp GEMM: C(16x96) = A(rows r0..r0+15, k 0..95) x B([n][k], bf16x2 packed, pitch PB)
__device__ __forceinline__ void wgemm12(const uint32* __restrict__ A,
                                        const uint32* __restrict__ B,
                                        int r0, int lane, float c[12][4]) {
    const int g = lane >> 2, tg = lane & 3;
    const uint32* Ap = A + (r0 + g) * PB + tg;
    const uint32* Bp = B + g * PB + tg;
#pragma unroll
    for (int ks = 0; ks < 6; ++ks) {
        const int kb = ks * 8;
        uint32 a0 = Ap[kb], a1 = Ap[8 * PB + kb], a2 = Ap[kb + 4], a3 = Ap[8 * PB + kb + 4];
#pragma unroll
        for (int n = 0; n < 12; ++n) {
            uint32 b0 = Bp[n * 8 * PB + kb], b1 = Bp[n * 8 * PB + kb + 4];
            mma16(c[n], a0, a1, a2, a3, b0, b1);
        }
    }
}

// scalar 6x3 microtile GEMM for pre (512 threads: ty=tid>>5 rows, tx=tid&31 cols)
template<int AMODE, int PPB>
__device__ __forceinline__ void gemm96s(const float* __restrict__ A,
                                        const float* __restrict__ B,
                                        int i0, int j0, float acc[6][3]) {
#pragma unroll 4
    for (int k = 0; k < 96; ++k) {
        float bv[3];
#pragma unroll
        for (int p = 0; p < 3; ++p) bv[p] = B[k * PPB + j0 + p];
#pragma unroll
        for (int i = 0; i < 6; ++i) {
            float a = (AMODE == 0) ? A[k * TP + i0 + i] : A[(i0 + i) * 96 + k];
#pragma unroll
            for (int p = 0; p < 3; ++p) acc[i][p] += a * bv[p];
        }
    }
}

// ---- 1) GroupNorm
__global__ void gn_kernel(const float* __restrict__ x,
                          const float* __restrict__ gamma,
                          const float* __restrict__ beta) {
    const int b = blockIdx.x, g = blockIdx.y, tid = threadIdx.x;
    const float* xp = x + b * 9216 + g * 1152;
    float vals[9], sum = 0.f, sq = 0.f;
#pragma unroll
    for (int t = 0; t < 9; ++t) {
        float v = xp[tid + t * 128];
        vals[t] = v; sum += v; sq += v * v;
    }
    __shared__ float s1[128], s2[128];
    s1[tid] = sum; s2[tid] = sq;
    __syncthreads();
    for (int o = 64; o > 0; o >>= 1) {
        if (tid < o) { s1[tid] += s1[tid + o]; s2[tid] += s2[tid + o]; }
        __syncthreads();
    }
    const float mean = s1[0] * (1.f / 1152.f);
    const float var  = s2[0] * (1.f / 1152.f) - mean * mean;
    const float rstd = rsqrtf(var + 1e-5f);
#pragma unroll
    for (int t = 0; t < 9; ++t) {
        int e = tid + t * 128;
        int ch = g * 12 + e / 96;
        g_xn[b * 9216 + g * 1152 + e] = (vals[t] - mean) * rstd * gamma[ch] + beta[ch];
    }
}

// ---- 2) Precompute, 512 threads (6x3 microtiles), stores M^T/N^T bf16x2 packed
__global__ __launch_bounds__(512, 1)
void pre_kernel(const float* __restrict__ Wq, const float* __restrict__ bq,
                const float* __restrict__ Wk, const float* __restrict__ bk,
                const float* __restrict__ Wv, const float* __restrict__ bv,
                const float* __restrict__ Wo, const float* __restrict__ bo) {
    const int h = blockIdx.x, m = blockIdx.y, tid = threadIdx.x;
    extern __shared__ float sm[];
    float* bufA = sm;
    float* bufB = sm + 9216;
    const float inv = rsqrtf(96.0f);
    const int tx = tid & 31, ty = tid >> 5;
    const int i0 = ty * 6, j0 = tx * 3;

    if (m == 0) {
        for (int idx = tid; idx < 9216; idx += 512) {
            int i = idx / 96, d = idx % 96;
            bufA[idx]        = Wq[i * 768 + h * 96 + d];
            bufB[d * TP + i] = Wk[i * 768 + h * 96 + d];
        }
        __syncthreads();
        float acc[6][3];
#pragma unroll
        for (int i = 0; i < 6; ++i) for (int p = 0; p < 3; ++p) acc[i][p] = 0.f;
        gemm96s<1, TP>(bufA, bufB, i0, j0, acc);   // M = Wq_h Wk_h^T
#pragma unroll
        for (int s = 0; s < 3; ++s)
#pragma unroll
            for (int p = 0; p < 3; ++p)
                g_M[h * 4608 + (j0 + p) * 48 + (i0 >> 1) + s] =
                    f2bf2(acc[2 * s][p] * inv, acc[2 * s + 1][p] * inv);
        if (tid < 96) {
            float a = 0.f, c = 0.f;
            for (int d = 0; d < 96; ++d) {
                a += bufA[tid * 96 + d] * bk[h * 96 + d];
                c += bufB[d * TP + tid] * bq[h * 96 + d];
            }
            g_u[h * 96 + tid] = a * inv;
            g_w[h * 96 + tid] = c * inv;
        }
        if (tid == 0) {
            float cs = 0.f;
            for (int d = 0; d < 96; ++d) cs += bq[h * 96 + d] * bk[h * 96 + d];
            g_cc[h] = cs * inv;
        }
        if (h == 0 && tid >= 128 && tid < 224) {
            int c = tid - 128;
            float s = bo[c];
            for (int j = 0; j < 768; ++j) s += bv[j] * Wo[j * 96 + c];
            g_bp[c] = s;
        }
    } else {
        for (int idx = tid; idx < 9216; idx += 512) {
            int i = idx / 96, d = idx % 96;
            bufA[idx] = Wv[i * 768 + h * 96 + d];
            bufB[idx] = Wo[h * 9216 + idx];
        }
        __syncthreads();
        float acc[6][3];
#pragma unroll
        for (int i = 0; i < 6; ++i) for (int p = 0; p < 3; ++p) acc[i][p] = 0.f;
        gemm96s<1, 96>(bufA, bufB, i0, j0, acc);   // N = Wv_h Wo_h
#pragma unroll
        for (int s = 0; s < 3; ++s)
#pragma unroll
            for (int p = 0; p < 3; ++p)
                g_N[h * 4608 + (j0 + p) * 48 + (i0 >> 1) + s] =
                    f2bf2(acc[2 * s][p], acc[2 * s + 1][p]);
    }
}

// ---- 3) Attention: bf16 m16n8k16 mma, 6 warps x (16 x 96) tiles, occ=3
__global__ __launch_bounds__(192, 3)
void attn_kernel() {
    const int b = blockIdx.x, h = blockIdx.y;
    extern __shared__ uint32 smu[];
    uint32* tS = smu;             // t(bf16x2) -> X2^T ; pads 48=UV,49=WV,50=RV,51=ZV (fp32)
    uint32* W  = smu + 96 * PB;   // M^T -> N^T
    uint32* Y  = smu + 2 * 96 * PB;// X1 -> P
    float* tSf = (float*)tS;

    const int tid = threadIdx.x;
    const int lane = tid & 31, wid = tid >> 5;  // 6 warps
    const int r0 = wid * 16;
    const int g = lane >> 2, tg = lane & 3;
    const float NEGINF = __int_as_float(0xff800000);

    {
        const float4* xb4 = (const float4*)(g_xn + b * 9216);
        const uint4*  Mh4 = (const uint4*)(g_M + h * 4608);
#pragma unroll
        for (int r = 0; r < 6; ++r) {
            int idx = tid + r * 192;
            int rr = idx / 12, o = idx - rr * 12;
            float4 v0 = xb4[rr * 24 + 2 * o];
            float4 v1 = xb4[rr * 24 + 2 * o + 1];
            uint4 wv;
            wv.x = f2bf2(v0.x, v0.y); wv.y = f2bf2(v0.z, v0.w);
            wv.z = f2bf2(v1.x, v1.y); wv.w = f2bf2(v1.z, v1.w);
            *(uint4*)(tS + rr * PB + o * 4) = wv;
            *(uint4*)(W  + rr * PB + o * 4) = Mh4[idx];
        }
        if (tid < 96) { tSf[tid * PB + 48] = g_u[h * 96 + tid];
                        tSf[tid * PB + 49] = g_w[h * 96 + tid]; }
    }
    __syncthreads();   // A

    if (tid < 96) {
        float a = 0.f;
        for (int w = 0; w < 48; ++w) {
            float2 t2 = bf2f(tS[tid * PB + w]);
            a += t2.x * tSf[(2 * w) * PB + 48] + t2.y * tSf[(2 * w + 1) * PB + 48];
        }
        tSf[tid * PB + 50] = a;                       // RV
    } else {
        const int j = tid - 96;
        float a = 0.f;
        for (int w = 0; w < 48; ++w) {
            float2 t2 = bf2f(tS[j * PB + w]);
            a += t2.x * tSf[(2 * w) * PB + 49] + t2.y * tSf[(2 * w + 1) * PB + 49];
        }
        tSf[j * PB + 51] = a;                         // ZV
    }

    // GEMM1: X1 = t * M
    {
        float c[12][4];
#pragma unroll
        for (int n = 0; n < 12; ++n) for (int q = 0; q < 4; ++q) c[n][q] = 0.f;
        wgemm12(tS, W, r0, lane, c);
#pragma unroll
        for (int n = 0; n < 12; ++n) {
            const int wcol = n * 4 + tg, row = r0 + g;
            Y[row * PB + wcol]       = f2bf2(c[n][0], c[n][1]);
            Y[(row + 8) * PB + wcol] = f2bf2(c[n][2], c[n][3]);
        }
    }
    __syncthreads();   // B

    uint4 nreg[6];
    {
        const uint4* Nh4 = (const uint4*)(g_N + h * 4608);
#pragma unroll
        for (int r = 0; r < 6; ++r) nreg[r] = Nh4[tid + r * 192];
    }

    // GEMM2 + warp-local causal softmax
    {
        float sv[12][4];
#pragma unroll
        for (int n = 0; n < 12; ++n) for (int q = 0; q < 4; ++q) sv[n][q] = 0.f;
        wgemm12(Y, tS, r0, lane, sv);

        const int i0r = r0 + g, i1r = r0 + g + 8;
        const float ccv = g_cc[h];
        const float ri0 = tSf[i0r * PB + 50] + ccv;
        const float ri1 = tSf[i1r * PB + 50] + ccv;
        float m0 = NEGINF, m1 = NEGINF;
#pragma unroll
        for (int n = 0; n < 12; ++n) {
            const int j0 = n * 8 + 2 * tg, j1 = j0 + 1;
            const float z0 = tSf[j0 * PB + 51], z1 = tSf[j1 * PB + 51];
            float v00 = (j0 <= i0r) ? sv[n][0] + ri0 + z0 : NEGINF;
            float v01 = (j1 <= i0r) ? sv[n][1] + ri0 + z1 : NEGINF;
            float v10 = (j0 <= i1r) ? sv[n][2] + ri1 + z0 : NEGINF;
            float v11 = (j1 <= i1r) ? sv[n][3] + ri1 + z1 : NEGINF;
            sv[n][0] = v00; sv[n][1] = v01; sv[n][2] = v10; sv[n][3] = v11;
            m0 = fmaxf(m0, fmaxf(v00, v01));
            m1 = fmaxf(m1, fmaxf(v10, v11));
        }
        m0 = fmaxf(m0, __shfl_xor_sync(0xffffffffu, m0, 1));
        m0 = fmaxf(m0, __shfl_xor_sync(0xffffffffu, m0, 2));
        m1 = fmaxf(m1, __shfl_xor_sync(0xffffffffu, m1, 1));
        m1 = fmaxf(m1, __shfl_xor_sync(0xffffffffu, m1, 2));
        float s0 = 0.f, s1 = 0.f;
#pragma unroll
        for (int n = 0; n < 12; ++n) {
            float e0 = __expf(sv[n][0] - m0), e1 = __expf(sv[n][1] - m0);
            float e2 = __expf(sv[n][2] - m1), e3 = __expf(sv[n][3] - m1);
            sv[n][0] = e0; sv[n][1] = e1; sv[n][2] = e2; sv[n][3] = e3;
            s0 += e0 + e1; s1 += e2 + e3;
        }
        s0 += __shfl_xor_sync(0xffffffffu, s0, 1);
        s0 += __shfl_xor_sync(0xffffffffu, s0, 2);
        s1 += __shfl_xor_sync(0xffffffffu, s1, 1);
        s1 += __shfl_xor_sync(0xffffffffu, s1, 2);
        const float is0 = 1.0f / s0, is1 = 1.0f / s1;
#pragma unroll
        for (int n = 0; n < 12; ++n) {
            const int wcol = n * 4 + tg;
            Y[i0r * PB + wcol] = f2bf2(sv[n][0] * is0, sv[n][1] * is0);
            Y[i1r * PB + wcol] = f2bf2(sv[n][2] * is1, sv[n][3] * is1);
        }
    }

#pragma unroll
    for (int r = 0; r < 6; ++r) {
        int idx = tid + r * 192;
        int rr = idx / 12, o = idx - rr * 12;
        *(uint4*)(W + rr * PB + o * 4) = nreg[r];
    }
    __syncthreads();   // C

    // GEMM3': X2^T = N^T x t (rows l)
    {
        float c[12][4];
#pragma unroll
        for (int n = 0; n < 12; ++n) for (int q = 0; q < 4; ++q) c[n][q] = 0.f;
        wgemm12(W, tS, r0, lane, c);
        __syncthreads();   // D
#pragma unroll
        for (int n = 0; n < 12; ++n) {
            const int wcol = n * 4 + tg, row = r0 + g;
            tS[row * PB + wcol]       = f2bf2(c[n][0], c[n][1]);
            tS[(row + 8) * PB + wcol] = f2bf2(c[n][2], c[n][3]);
        }
    }
    __syncthreads();   // E

    // GEMM4: AV = P * X2 -> g_part (bf16x2 packed)
    {
        float c[12][4];
#pragma unroll
        for (int n = 0; n < 12; ++n) for (int q = 0; q < 4; ++q) c[n][q] = 0.f;
        wgemm12(Y, tS, r0, lane, c);
        uint32* dst = g_part + (h * 96 + b) * 4608;
#pragma unroll
        for (int n = 0; n < 12; ++n) {
            const int wcol = n * 4 + tg, row = r0 + g;
            dst[row * 48 + wcol]       = f2bf2(c[n][0], c[n][1]);
            dst[(row + 8) * 48 + wcol] = f2bf2(c[n][2], c[n][3]);
        }
    }
}

// ---- 4) Fused head-reduce + broadcast, s-split, bf16 partial reads
__global__ __launch_bounds__(384)
void redbc_kernel(float* __restrict__ out) {
    __shared__ __align__(16) float O_s[4608];   // 48 rows x 96
    const int bt = blockIdx.x, j = blockIdx.y, sh = blockIdx.z;
    const int tid = threadIdx.x;
    float4* Os4 = (float4*)O_s;
    const float4* bp4 = (const float4*)g_bp;
#pragma unroll
    for (int r = 0; r < 3; ++r) {
        int idx = tid + r * 384;                 // 1152 float4-granules = 48 x 24
        float4 a = bp4[idx % 24];
#pragma unroll
        for (int h = 0; h < 8; ++h) {
            uint2 p = ((const uint2*)(g_part + (size_t)h * 442368
                                             + (size_t)j * 4608
                                             + (size_t)sh * 2304))[idx];
            float2 lo = bf2f(p.x), hi = bf2f(p.y);
            a.x += lo.x; a.y += lo.y; a.z += hi.x; a.w += hi.y;
        }
        Os4[idx] = a;
    }
    const int b_i = tid / 24;       // 0..15
    const int q   = tid - b_i * 24; // 0..23
    const int bg  = bt * 16 + b_i;
    const float4 xnv = *(const float4*)(g_xn + (size_t)bg * 9216 + j * 96 + q * 4);
    __syncthreads();
    float* dst = out + ((size_t)bg * 96 + (size_t)j) * 9216 + (size_t)(sh * 48) * 96 + q * 4;
#pragma unroll 8
    for (int s = 0; s < 48; ++s) {
        float4 o = Os4[s * 24 + q];
        float4 v = make_float4(o.x + xnv.x, o.y + xnv.y, o.z + xnv.z, o.w + xnv.w);
        __stcs((float4*)(dst + s * 96), v);
    }
}

extern "C" void kernel_launch(void* const* d_in, const int* in_sizes, int n_in,
                              void* d_out, int out_size) {
    const float* x     = (const float*)d_in[0];
    const float* Wq    = (const float*)d_in[1];
    const float* bq    = (const float*)d_in[2];
    const float* Wk    = (const float*)d_in[3];
    const float* bk    = (const float*)d_in[4];
    const float* Wv    = (const float*)d_in[5];
    const float* bv    = (const float*)d_in[6];
    const float* Wo    = (const float*)d_in[7];
    const float* bo    = (const float*)d_in[8];
    const float* gamma = (const float*)d_in[9];
    const float* beta  = (const float*)d_in[10];
    float* out = (float*)d_out;

    const int pre_smem  = (9216 + 96 * TP) * 4;
    const int attn_smem = 3 * 96 * PB * 4;   // 59,904 B -> 3 CTAs/SM
    cudaFuncSetAttribute(pre_kernel,  cudaFuncAttributeMaxDynamicSharedMemorySize, pre_smem);
    cudaFuncSetAttribute(attn_kernel, cudaFuncAttributeMaxDynamicSharedMemorySize, attn_smem);

    gn_kernel<<<dim3(96, 8), 128>>>(x, gamma, beta);
    pre_kernel<<<dim3(8, 2), 512, pre_smem>>>(Wq, bq, Wk, bk, Wv, bv, Wo, bo);
    attn_kernel<<<dim3(96, 8), 192, attn_smem>>>();
    redbc_kernel<<<dim3(6, 96, 2), 384>>>(out);
}